// round 1
// baseline (speedup 1.0000x reference)
#include <cuda_runtime.h>
#include <cuda_bf16.h>
#include <math.h>

// ---------------------------------------------------------------------------
// Attention2D: GroupNorm -> q,k,v 1x1 convs -> softmax attention -> out conv
// b=4, c=512, h=w=64 (hw=4096), 32 groups.
// Round 1: fp32 SIMT baseline. Generic strided GEMM covers all 6 GEMMs.
// ---------------------------------------------------------------------------

#define B_  4
#define C_  512
#define HW_ 4096
#define NG_ 32
#define CPG_ (C_ / NG_)          // 16 channels per group
#define GRP_ELEMS (CPG_ * HW_)   // 65536

// Scratch (static device globals; no runtime allocation allowed)
__device__ float g_x [ (size_t)B_ * C_ * HW_ ];   // normed input      32 MB
__device__ float g_q [ (size_t)B_ * C_ * HW_ ];   // q proj            32 MB
__device__ float g_k [ (size_t)B_ * C_ * HW_ ];   // k proj            32 MB
__device__ float g_v [ (size_t)B_ * C_ * HW_ ];   // v proj            32 MB
__device__ float g_st[ (size_t)B_ * HW_ * HW_ ];  // scores^T / attn  256 MB
__device__ float g_o [ (size_t)B_ * C_ * HW_ ];   // attn output       32 MB

// ---------------------------------------------------------------------------
// GroupNorm: one block per (batch, group). Two passes over 65536 elements.
// ---------------------------------------------------------------------------
__global__ __launch_bounds__(256) void groupnorm_kernel(
    const float* __restrict__ x, const float* __restrict__ gamma,
    const float* __restrict__ beta, float* __restrict__ y)
{
    int b = blockIdx.x / NG_;
    int g = blockIdx.x % NG_;
    size_t base = ((size_t)b * C_ + (size_t)g * CPG_) * HW_;
    int t = threadIdx.x;

    float s = 0.f, ss = 0.f;
    for (int i = t; i < GRP_ELEMS; i += 256) {
        float v = x[base + i];
        s += v; ss += v * v;
    }
    // block reduction
    __shared__ float rs[8], rss[8];
    #pragma unroll
    for (int o = 16; o; o >>= 1) {
        s  += __shfl_xor_sync(0xffffffffu, s,  o);
        ss += __shfl_xor_sync(0xffffffffu, ss, o);
    }
    if ((t & 31) == 0) { rs[t >> 5] = s; rss[t >> 5] = ss; }
    __syncthreads();
    float ts = 0.f, tss = 0.f;
    #pragma unroll
    for (int i = 0; i < 8; i++) { ts += rs[i]; tss += rss[i]; }
    float inv_n = 1.0f / (float)GRP_ELEMS;
    float mu  = ts * inv_n;
    float var = tss * inv_n - mu * mu;
    float rstd = rsqrtf(var + 1e-6f);

    for (int i = t; i < GRP_ELEMS; i += 256) {
        int ch = g * CPG_ + i / HW_;
        float v = x[base + i];
        y[base + i] = (v - mu) * rstd * gamma[ch] + beta[ch];
    }
}

// ---------------------------------------------------------------------------
// Generic strided fp32 GEMM.
//   C[b][m][n] = alpha * ( sum_k A(b,m,k) * B(b,k,n) + bias[m] + res[b][m][n] )
// A element: A + b*a_sb + m*a_sm + k*a_sk
// B element: B + b*b_sb + k*b_sk + n*b_sn
// C, res: row-major [M,N], batch strides c_sb / r_sb.
// Tiles: 128x128x16, 256 threads, 8x8 per thread (split 4+4 rows/cols).
// Requires M%128==0, N%128==0, K%16==0 (true for all uses here).
// ---------------------------------------------------------------------------
#define BM 128
#define BN 128
#define BK 16

__global__ __launch_bounds__(256) void gemm_kernel(
    const float* __restrict__ A, long a_sm, long a_sk, long a_sb,
    const float* __restrict__ Bp, long b_sk, long b_sn, long b_sb,
    float* __restrict__ C, long c_sb,
    const float* __restrict__ bias,
    const float* __restrict__ res, long r_sb,
    float alpha, int M, int N, int K)
{
    __shared__ float As[BK][BM + 1];
    __shared__ float Bs[BK][BN + 1];

    int bz = blockIdx.z;
    const float* Ab = A  + (size_t)bz * a_sb;
    const float* Bb = Bp + (size_t)bz * b_sb;
    float*       Cb = C  + (size_t)bz * c_sb;
    const float* Rb = res ? res + (size_t)bz * r_sb : nullptr;

    int m0 = blockIdx.y * BM;
    int n0 = blockIdx.x * BN;
    int tid = threadIdx.x;
    int tr = tid >> 4;   // 0..15
    int tc = tid & 15;   // 0..15

    float acc[8][8];
    #pragma unroll
    for (int i = 0; i < 8; i++)
        #pragma unroll
        for (int j = 0; j < 8; j++) acc[i][j] = 0.f;

    for (int k0 = 0; k0 < K; k0 += BK) {
        // ---- load A tile (BM x BK) into As[k][m] ----
        if (a_sk == 1) {
            // k-contiguous source: each thread grabs 8 consecutive k
            #pragma unroll
            for (int e = 0; e < 8; e++) {
                int idx = tid * 8 + e;
                int k = idx & (BK - 1);
                int m = idx >> 4;
                As[k][m] = Ab[(long)(m0 + m) * a_sm + (k0 + k)];
            }
        } else {
            // m-contiguous source (a_sm == 1)
            #pragma unroll
            for (int e = 0; e < 8; e++) {
                int idx = tid + e * 256;
                int m = idx & (BM - 1);
                int k = idx >> 7;
                As[k][m] = Ab[(long)(m0 + m) + (long)(k0 + k) * a_sk];
            }
        }
        // ---- load B tile (BK x BN) into Bs[k][n] ----
        if (b_sn == 1) {
            #pragma unroll
            for (int e = 0; e < 8; e++) {
                int idx = tid + e * 256;
                int n = idx & (BN - 1);
                int k = idx >> 7;
                Bs[k][n] = Bb[(long)(k0 + k) * b_sk + (n0 + n)];
            }
        } else {
            // k-contiguous source (b_sk == 1)
            #pragma unroll
            for (int e = 0; e < 8; e++) {
                int idx = tid * 8 + e;
                int k = idx & (BK - 1);
                int n = idx >> 4;
                Bs[k][n] = Bb[(long)(k0 + k) + (long)(n0 + n) * b_sn];
            }
        }
        __syncthreads();

        #pragma unroll
        for (int kk = 0; kk < BK; kk++) {
            float a[8], bv[8];
            #pragma unroll
            for (int i = 0; i < 4; i++) {
                a[i]     = As[kk][tr * 4 + i];
                a[i + 4] = As[kk][64 + tr * 4 + i];
            }
            #pragma unroll
            for (int j = 0; j < 4; j++) {
                bv[j]     = Bs[kk][tc * 4 + j];
                bv[j + 4] = Bs[kk][64 + tc * 4 + j];
            }
            #pragma unroll
            for (int i = 0; i < 8; i++)
                #pragma unroll
                for (int j = 0; j < 8; j++)
                    acc[i][j] = fmaf(a[i], bv[j], acc[i][j]);
        }
        __syncthreads();
    }

    // ---- epilogue ----
    #pragma unroll
    for (int i = 0; i < 8; i++) {
        int row = (i < 4) ? (tr * 4 + i) : (64 + tr * 4 + (i - 4));
        int m = m0 + row;
        float bia = bias ? bias[m] : 0.f;
        #pragma unroll
        for (int j = 0; j < 8; j++) {
            int col = (j < 4) ? (tc * 4 + j) : (64 + tc * 4 + (j - 4));
            int n = n0 + col;
            float v = acc[i][j] + bia;
            if (Rb) v += Rb[(long)m * N + n];
            Cb[(long)m * N + n] = v * alpha;
        }
    }
}

// ---------------------------------------------------------------------------
// Row softmax over g_st rows (length 4096). One block per row, 256 threads,
// 16 elems per thread kept in registers.
// ---------------------------------------------------------------------------
__global__ __launch_bounds__(256) void softmax_kernel(float* __restrict__ st)
{
    size_t row = ((size_t)blockIdx.y * HW_ + blockIdx.x) * HW_;
    float* p = st + row;
    int t = threadIdx.x;

    float v[16];
    float mx = -1e30f;
    #pragma unroll
    for (int e = 0; e < 16; e++) {
        v[e] = p[t + e * 256];
        mx = fmaxf(mx, v[e]);
    }
    __shared__ float red[8];
    #pragma unroll
    for (int o = 16; o; o >>= 1) mx = fmaxf(mx, __shfl_xor_sync(0xffffffffu, mx, o));
    if ((t & 31) == 0) red[t >> 5] = mx;
    __syncthreads();
    float bm = red[0];
    #pragma unroll
    for (int i = 1; i < 8; i++) bm = fmaxf(bm, red[i]);
    __syncthreads();

    float s = 0.f;
    #pragma unroll
    for (int e = 0; e < 16; e++) {
        v[e] = expf(v[e] - bm);
        s += v[e];
    }
    #pragma unroll
    for (int o = 16; o; o >>= 1) s += __shfl_xor_sync(0xffffffffu, s, o);
    if ((t & 31) == 0) red[t >> 5] = s;
    __syncthreads();
    float ts = 0.f;
    #pragma unroll
    for (int i = 0; i < 8; i++) ts += red[i];
    float inv = 1.0f / ts;
    #pragma unroll
    for (int e = 0; e < 16; e++) p[t + e * 256] = v[e] * inv;
}

// ---------------------------------------------------------------------------
// Host launcher
// ---------------------------------------------------------------------------
extern "C" void kernel_launch(void* const* d_in, const int* in_sizes, int n_in,
                              void* d_out, int out_size)
{
    const float* q     = (const float*)d_in[0];
    const float* gamma = (const float*)d_in[1];
    const float* beta  = (const float*)d_in[2];
    const float* wq    = (const float*)d_in[3];
    const float* bq    = (const float*)d_in[4];
    const float* wk    = (const float*)d_in[5];
    const float* bk    = (const float*)d_in[6];
    const float* wv    = (const float*)d_in[7];
    const float* bv    = (const float*)d_in[8];
    const float* wo    = (const float*)d_in[9];
    const float* bo    = (const float*)d_in[10];
    float* out = (float*)d_out;

    float *x, *qp, *kp, *vp, *st, *o;
    cudaGetSymbolAddress((void**)&x,  g_x);
    cudaGetSymbolAddress((void**)&qp, g_q);
    cudaGetSymbolAddress((void**)&kp, g_k);
    cudaGetSymbolAddress((void**)&vp, g_v);
    cudaGetSymbolAddress((void**)&st, g_st);
    cudaGetSymbolAddress((void**)&o,  g_o);

    const long CB = (long)C_ * HW_;        // 512*4096 per-batch stride
    const long SB = (long)HW_ * HW_;       // 4096*4096 per-batch stride

    // 1. GroupNorm
    groupnorm_kernel<<<B_ * NG_, 256>>>(q, gamma, beta, x);

    // 2. q/k/v projections: C[oc,p] = W[oc,ic] * X[ic,p] + bias
    dim3 gConv(HW_ / BN, C_ / BM, B_);   // (32, 4, 4)
    gemm_kernel<<<gConv, 256>>>(wq, C_, 1, 0,  x, HW_, 1, CB,  qp, CB,
                                bq, nullptr, 0, 1.0f, C_, HW_, C_);
    gemm_kernel<<<gConv, 256>>>(wk, C_, 1, 0,  x, HW_, 1, CB,  kp, CB,
                                bk, nullptr, 0, 1.0f, C_, HW_, C_);
    gemm_kernel<<<gConv, 256>>>(wv, C_, 1, 0,  x, HW_, 1, CB,  vp, CB,
                                bv, nullptr, 0, 1.0f, C_, HW_, C_);

    // 3. scores^T: ST[j,i] = scale * sum_c Q[c,j] * K[c,i]
    //    A(m=j,k=c)=qp[c,j] -> a_sm=1, a_sk=HW; B(k=c,n=i)=kp[c,i] -> b_sk=HW, b_sn=1
    const float scale = 0.044194173824159216f;  // 512^-0.5
    dim3 gS(HW_ / BN, HW_ / BM, B_);     // (32, 32, 4)
    gemm_kernel<<<gS, 256>>>(qp, 1, HW_, CB,  kp, HW_, 1, CB,  st, SB,
                             nullptr, nullptr, 0, scale, HW_, HW_, C_);

    // 4. softmax over keys i (rows of ST are contiguous in i)
    softmax_kernel<<<dim3(HW_, B_), 256>>>(st);

    // 5. O[c,j] = sum_i V[c,i] * ST[j,i]
    //    A(m=c,k=i)=vp -> a_sm=HW, a_sk=1; B(k=i,n=j)=st[j,i] -> b_sk=1, b_sn=HW
    gemm_kernel<<<gConv, 256>>>(vp, HW_, 1, CB,  st, 1, HW_, SB,  o, CB,
                                nullptr, nullptr, 0, 1.0f, C_, HW_, HW_);

    // 6. final: out = (Wo*O + bo + q_in) * INV_SQRT2
    gemm_kernel<<<gConv, 256>>>(wo, C_, 1, 0,  o, HW_, 1, CB,  out, CB,
                                bo, q, CB, 0.7071067811865476f, C_, HW_, C_);
}

// round 3
// speedup vs baseline: 7.9025x; 7.9025x over previous
#include <cuda_runtime.h>
#include <cuda_fp16.h>
#include <cstdint>
#include <math.h>

// ---------------------------------------------------------------------------
// Attention2D on GB300 (sm_103 family target): GroupNorm -> q,k,v 1x1 conv ->
// softmax attention -> out conv.  b=4, c=512, hw=4096.
// Round 3: all GEMMs via mma.sync m16n8k16 fp16 (fp32 accumulate).
// Every GEMM is D = A * B^T with K-major fp16 A and B:
//   Xt[j][c] (normed, transposed, fp16)
//   Qt[j][c] = Xt @ Wq^T + bq ; Kt[i][c] likewise
//   V [c][i] = Wv @ Xt^T + bv
//   ST[j][i] = scale * Qt @ Kt^T        (fp16; softmax over i, in place)
//   Ot[j][c] = ST @ V^T
//   out[c][j] = (Wo @ Ot^T + bo + q_in) * inv_sqrt2   (fp32)
// ---------------------------------------------------------------------------

#define B_  4
#define C_  512
#define HW_ 4096
#define NG_ 32
#define CPG_ (C_ / NG_)
#define GRP_ELEMS (CPG_ * HW_)

__device__ __align__(256) __half g_xt[(size_t)B_ * HW_ * C_];   // 16 MB
__device__ __align__(256) __half g_qt[(size_t)B_ * HW_ * C_];   // 16 MB
__device__ __align__(256) __half g_kt[(size_t)B_ * HW_ * C_];   // 16 MB
__device__ __align__(256) __half g_v [(size_t)B_ * C_ * HW_];   // 16 MB
__device__ __align__(256) __half g_st[(size_t)B_ * HW_ * HW_];  // 128 MB
__device__ __align__(256) __half g_ot[(size_t)B_ * HW_ * C_];   // 16 MB
__device__ __align__(256) __half g_wh[4][(size_t)C_ * C_];      // 2 MB
__device__ float2 g_stats[B_ * NG_];

// ============================ small kernels ================================
__global__ __launch_bounds__(256) void f2h_kernel(
    const float* __restrict__ w, __half* __restrict__ o, int n)
{
    int i = blockIdx.x * blockDim.x + threadIdx.x;
    if (i < n) o[i] = __float2half(w[i]);
}

__global__ __launch_bounds__(256) void gn_stats(
    const float* __restrict__ x, float2* __restrict__ stats)
{
    int b = blockIdx.x / NG_, g = blockIdx.x % NG_;
    size_t base = ((size_t)b * C_ + (size_t)g * CPG_) * HW_;
    int t = threadIdx.x;
    float s = 0.f, ss = 0.f;
    for (int i = t; i < GRP_ELEMS; i += 256) {
        float v = x[base + i];
        s += v; ss += v * v;
    }
    __shared__ float rs[8], rss[8];
    #pragma unroll
    for (int o = 16; o; o >>= 1) {
        s  += __shfl_xor_sync(0xffffffffu, s,  o);
        ss += __shfl_xor_sync(0xffffffffu, ss, o);
    }
    if ((t & 31) == 0) { rs[t >> 5] = s; rss[t >> 5] = ss; }
    __syncthreads();
    if (t == 0) {
        float ts = 0.f, tss = 0.f;
        #pragma unroll
        for (int i = 0; i < 8; i++) { ts += rs[i]; tss += rss[i]; }
        float inv_n = 1.0f / (float)GRP_ELEMS;
        float mu = ts * inv_n;
        float var = tss * inv_n - mu * mu;
        stats[blockIdx.x] = make_float2(mu, rsqrtf(var + 1e-6f));
    }
}

// GroupNorm apply + transpose: x[b][c][j] (fp32) -> xt[b][j][c] (fp16)
__global__ __launch_bounds__(256) void gn_apply_t(
    const float* __restrict__ x, const float2* __restrict__ stats,
    const float* __restrict__ gamma, const float* __restrict__ beta,
    __half* __restrict__ xt)
{
    __shared__ float tile[32][33];
    int j0 = blockIdx.x * 32, c0 = blockIdx.y * 32, b = blockIdx.z;
    int tx = threadIdx.x & 31, ty = threadIdx.x >> 5;
    size_t xb = (size_t)b * C_ * HW_;
    #pragma unroll
    for (int it = 0; it < 4; it++) {
        int c = c0 + ty + it * 8;
        float v = x[xb + (size_t)c * HW_ + j0 + tx];
        float2 s = stats[b * NG_ + (c >> 4)];
        tile[ty + it * 8][tx] = (v - s.x) * s.y * gamma[c] + beta[c];
    }
    __syncthreads();
    size_t tb = (size_t)b * HW_ * C_;
    #pragma unroll
    for (int it = 0; it < 4; it++) {
        int j = j0 + ty + it * 8;
        xt[tb + (size_t)j * C_ + c0 + tx] = __float2half(tile[tx][ty + it * 8]);
    }
}

// ========================= fp16 mma.sync GEMM ==============================
// D[m][n] = alpha*(sum_k A[m][k]*B[n][k] + bias_m[m] + bias_n[n] + res[m][n])
// 128x128 CTA tile, BK=64, 8 warps in 2(m) x 4(n), warp tile 64x32.
#define BM 128
#define BN 128
#define BK 64
#define SMEM_HALF (2 * 2 * BM * BK)   // [2 bufs][A+B] halves

__device__ __forceinline__ uint32_t smem_u32(const void* p) {
    uint32_t a;
    asm("{ .reg .u64 t; cvta.to.shared.u64 t, %1; cvt.u32.u64 %0, t; }"
        : "=r"(a) : "l"(p));
    return a;
}

// load one 128x64-half tile with SW128-style XOR swizzle (8 x 16B chunks/row)
__device__ __forceinline__ void load_tile_h(
    uint32_t sdst, const __half* __restrict__ src, long ld, int tid)
{
    #pragma unroll
    for (int i = 0; i < 4; i++) {
        int idx = tid + (i << 8);          // 0..1023
        int r = idx >> 3;
        int c = idx & 7;
        uint32_t sw = (uint32_t)r * 128 + (uint32_t)((c ^ (r & 7)) << 4);
        asm volatile("cp.async.cg.shared.global [%0], [%1], 16;"
                     :: "r"(sdst + sw), "l"(src + (long)r * ld + (c << 3))
                     : "memory");
    }
}

#define LDSM4(r0, r1, r2, r3, a)                                           \
    asm volatile("ldmatrix.sync.aligned.m8n8.x4.shared.b16 {%0,%1,%2,%3}, [%4];" \
                 : "=r"(r0), "=r"(r1), "=r"(r2), "=r"(r3) : "r"(a))

__global__ __launch_bounds__(256) void mm_h(
    const __half* __restrict__ A, long lda, long asb,
    const __half* __restrict__ Bp, long ldb, long bsb,
    __half* __restrict__ Ch, float* __restrict__ Cf, long ldc, long csb,
    const float* __restrict__ bias_m, const float* __restrict__ bias_n,
    const float* __restrict__ res, long rsb, float alpha, int T)
{
    extern __shared__ __half smem[];
    uint32_t sb = smem_u32(smem);
    const uint32_t sA[2] = { sb,               sb + 2 * BM * BK * 2 };
    const uint32_t sB[2] = { sb + BM * BK * 2, sb + 3 * BM * BK * 2 };

    int tid = threadIdx.x, lane = tid & 31, wid = tid >> 5;
    int wm = wid >> 2, wn = wid & 3;        // 2 x 4 warp grid
    int bz = blockIdx.z;
    int m0 = blockIdx.y * BM, n0 = blockIdx.x * BN;

    const __half* Ab = A  + (size_t)bz * asb + (size_t)m0 * lda;
    const __half* Bb = Bp + (size_t)bz * bsb + (size_t)n0 * ldb;

    float acc[4][4][4];
    #pragma unroll
    for (int i = 0; i < 4; i++)
        #pragma unroll
        for (int j = 0; j < 4; j++)
            #pragma unroll
            for (int k = 0; k < 4; k++) acc[i][j][k] = 0.f;

    // fragment address components (per thread, constant over k-steps)
    int a_r  = (lane & 7) | (((lane >> 3) & 1) << 3);  // row-in-16 for A
    int a_cs = lane >> 4;                               // chunk select 0/1
    int b_r  = (lane & 7) | (((lane >> 4) & 1) << 3);  // row-in-16 for B
    int b_cs = (lane >> 3) & 1;

    load_tile_h(sA[0], Ab, lda, tid);
    load_tile_h(sB[0], Bb, ldb, tid);
    asm volatile("cp.async.commit_group;");

    for (int t = 0; t < T; t++) {
        int c = t & 1;
        if (t + 1 < T) {
            load_tile_h(sA[c ^ 1], Ab + (size_t)(t + 1) * BK, lda, tid);
            load_tile_h(sB[c ^ 1], Bb + (size_t)(t + 1) * BK, ldb, tid);
            asm volatile("cp.async.commit_group;");
            asm volatile("cp.async.wait_group 1;");
        } else {
            asm volatile("cp.async.wait_group 0;");
        }
        __syncthreads();

        #pragma unroll
        for (int ks = 0; ks < 4; ks++) {
            uint32_t a[4][4], b[4][2];
            int ach = ks * 2 + a_cs;
            #pragma unroll
            for (int mt = 0; mt < 4; mt++) {
                int row = wm * 64 + mt * 16 + a_r;
                uint32_t addr = sA[c] + (uint32_t)row * 128
                              + (uint32_t)((ach ^ (row & 7)) << 4);
                LDSM4(a[mt][0], a[mt][1], a[mt][2], a[mt][3], addr);
            }
            int bch = ks * 2 + b_cs;
            #pragma unroll
            for (int p = 0; p < 2; p++) {
                int row = wn * 32 + p * 16 + b_r;
                uint32_t addr = sB[c] + (uint32_t)row * 128
                              + (uint32_t)((bch ^ (row & 7)) << 4);
                LDSM4(b[2 * p][0], b[2 * p][1], b[2 * p + 1][0], b[2 * p + 1][1], addr);
            }
            #pragma unroll
            for (int mt = 0; mt < 4; mt++)
                #pragma unroll
                for (int nt = 0; nt < 4; nt++)
                    asm volatile(
                        "mma.sync.aligned.m16n8k16.row.col.f32.f16.f16.f32 "
                        "{%0,%1,%2,%3}, {%4,%5,%6,%7}, {%8,%9}, {%0,%1,%2,%3};"
                        : "+f"(acc[mt][nt][0]), "+f"(acc[mt][nt][1]),
                          "+f"(acc[mt][nt][2]), "+f"(acc[mt][nt][3])
                        : "r"(a[mt][0]), "r"(a[mt][1]), "r"(a[mt][2]), "r"(a[mt][3]),
                          "r"(b[nt][0]), "r"(b[nt][1]));
        }
        __syncthreads();
    }

    // ------------------------------ epilogue -------------------------------
    int mb = m0 + wm * 64;
    int nb = n0 + wn * 32;
    int r0 = lane >> 2, c0 = (lane & 3) * 2;
    __half* Chb = Ch ? Ch + (size_t)bz * csb : nullptr;
    float*  Cfb = Cf ? Cf + (size_t)bz * csb : nullptr;
    const float* Rb = res ? res + (size_t)bz * rsb : nullptr;

    #pragma unroll
    for (int mt = 0; mt < 4; mt++) {
        #pragma unroll
        for (int h = 0; h < 2; h++) {
            int m = mb + mt * 16 + r0 + h * 8;
            float bmv = bias_m ? bias_m[m] : 0.f;
            #pragma unroll
            for (int nt = 0; nt < 4; nt++) {
                int n = nb + nt * 8 + c0;
                float v0 = acc[mt][nt][2 * h + 0];
                float v1 = acc[mt][nt][2 * h + 1];
                v0 += bmv; v1 += bmv;
                if (bias_n) { v0 += bias_n[n]; v1 += bias_n[n + 1]; }
                if (Rb) {
                    const float* rp = Rb + (size_t)m * ldc + n;
                    v0 += rp[0]; v1 += rp[1];
                }
                v0 *= alpha; v1 *= alpha;
                if (Chb) {
                    *reinterpret_cast<__half2*>(Chb + (size_t)m * ldc + n) =
                        __floats2half2_rn(v0, v1);
                } else {
                    float2 f2 = make_float2(v0, v1);
                    *reinterpret_cast<float2*>(Cfb + (size_t)m * ldc + n) = f2;
                }
            }
        }
    }
}

// ============================ Softmax (fp16, in place) =====================
__global__ __launch_bounds__(256) void softmax_h(__half* __restrict__ st)
{
    size_t row = ((size_t)blockIdx.y * HW_ + blockIdx.x) * HW_;
    __half2* p = reinterpret_cast<__half2*>(st + row);
    int t = threadIdx.x;

    float f[16];
    #pragma unroll
    for (int e = 0; e < 8; e++) {
        float2 v = __half22float2(p[t + e * 256]);
        f[2 * e] = v.x; f[2 * e + 1] = v.y;
    }
    float mx = -1e30f;
    #pragma unroll
    for (int e = 0; e < 16; e++) mx = fmaxf(mx, f[e]);
    __shared__ float red[8];
    #pragma unroll
    for (int o = 16; o; o >>= 1) mx = fmaxf(mx, __shfl_xor_sync(0xffffffffu, mx, o));
    if ((t & 31) == 0) red[t >> 5] = mx;
    __syncthreads();
    float bmx = red[0];
    #pragma unroll
    for (int i = 1; i < 8; i++) bmx = fmaxf(bmx, red[i]);
    __syncthreads();

    float s = 0.f;
    #pragma unroll
    for (int e = 0; e < 16; e++) { f[e] = expf(f[e] - bmx); s += f[e]; }
    #pragma unroll
    for (int o = 16; o; o >>= 1) s += __shfl_xor_sync(0xffffffffu, s, o);
    if ((t & 31) == 0) red[t >> 5] = s;
    __syncthreads();
    float ts = 0.f;
    #pragma unroll
    for (int i = 0; i < 8; i++) ts += red[i];
    float inv = 1.0f / ts;
    #pragma unroll
    for (int e = 0; e < 8; e++)
        p[t + e * 256] = __floats2half2_rn(f[2 * e] * inv, f[2 * e + 1] * inv);
}

// ============================ Launcher =====================================
extern "C" void kernel_launch(void* const* d_in, const int* in_sizes, int n_in,
                              void* d_out, int out_size)
{
    const float* q     = (const float*)d_in[0];
    const float* gamma = (const float*)d_in[1];
    const float* beta  = (const float*)d_in[2];
    const float* wq    = (const float*)d_in[3];
    const float* bq    = (const float*)d_in[4];
    const float* wk    = (const float*)d_in[5];
    const float* bk    = (const float*)d_in[6];
    const float* wv    = (const float*)d_in[7];
    const float* bv    = (const float*)d_in[8];
    const float* wo    = (const float*)d_in[9];
    const float* bo    = (const float*)d_in[10];
    float* out = (float*)d_out;

    __half *xt, *qt, *kt, *v, *st, *ot, *wh;
    float2* stats;
    cudaGetSymbolAddress((void**)&xt, g_xt);
    cudaGetSymbolAddress((void**)&qt, g_qt);
    cudaGetSymbolAddress((void**)&kt, g_kt);
    cudaGetSymbolAddress((void**)&v,  g_v);
    cudaGetSymbolAddress((void**)&st, g_st);
    cudaGetSymbolAddress((void**)&ot, g_ot);
    cudaGetSymbolAddress((void**)&wh, g_wh);
    cudaGetSymbolAddress((void**)&stats, g_stats);
    __half* wqh = wh;
    __half* wkh = wh + (size_t)C_ * C_;
    __half* wvh = wh + 2 * (size_t)C_ * C_;
    __half* woh = wh + 3 * (size_t)C_ * C_;

    static int smem_set = 0;
    if (!smem_set) {
        cudaFuncSetAttribute(mm_h, cudaFuncAttributeMaxDynamicSharedMemorySize,
                             SMEM_HALF * 2);
        smem_set = 1;
    }

    const long CB = (long)C_ * HW_;
    const long SB = (long)HW_ * HW_;
    const int  WN = C_ * C_;

    // 0. weights -> fp16
    f2h_kernel<<<(WN + 255) / 256, 256>>>(wq, wqh, WN);
    f2h_kernel<<<(WN + 255) / 256, 256>>>(wk, wkh, WN);
    f2h_kernel<<<(WN + 255) / 256, 256>>>(wv, wvh, WN);
    f2h_kernel<<<(WN + 255) / 256, 256>>>(wo, woh, WN);

    // 1. GroupNorm -> Xt[j][c] fp16
    gn_stats<<<B_ * NG_, 256>>>(q, stats);
    gn_apply_t<<<dim3(HW_ / 32, C_ / 32, B_), 256>>>(q, stats, gamma, beta, xt);

    // 2. Qt / Kt: M=4096(j), N=512(c), K=512
    dim3 gP(C_ / BN, HW_ / BM, B_);
    mm_h<<<gP, 256, SMEM_HALF * 2>>>(xt, C_, CB,  wqh, C_, 0,
                                     qt, nullptr, C_, CB,
                                     nullptr, bq, nullptr, 0, 1.0f, C_ / BK);
    mm_h<<<gP, 256, SMEM_HALF * 2>>>(xt, C_, CB,  wkh, C_, 0,
                                     kt, nullptr, C_, CB,
                                     nullptr, bk, nullptr, 0, 1.0f, C_ / BK);

    // 3. V[c][i]: M=512(c), N=4096(i), K=512
    dim3 gV(HW_ / BN, C_ / BM, B_);
    mm_h<<<gV, 256, SMEM_HALF * 2>>>(wvh, C_, 0,  xt, C_, CB,
                                     v, nullptr, HW_, CB,
                                     bv, nullptr, nullptr, 0, 1.0f, C_ / BK);

    // 4. ST[j][i] = scale * Qt @ Kt^T: M=N=4096, K=512
    dim3 gS(HW_ / BN, HW_ / BM, B_);
    mm_h<<<gS, 256, SMEM_HALF * 2>>>(qt, C_, CB,  kt, C_, CB,
                                     st, nullptr, HW_, SB,
                                     nullptr, nullptr, nullptr, 0,
                                     0.044194173824159216f, C_ / BK);

    // 5. softmax over i (rows contiguous)
    softmax_h<<<dim3(HW_, B_), 256>>>(st);

    // 6. Ot[j][c] = ST @ V^T: M=4096(j), N=512(c), K=4096
    mm_h<<<gP, 256, SMEM_HALF * 2>>>(st, HW_, SB,  v, HW_, CB,
                                     ot, nullptr, C_, CB,
                                     nullptr, nullptr, nullptr, 0, 1.0f, HW_ / BK);

    // 7. out[c][j] = (Wo @ Ot^T + bo + q) * inv_sqrt2: M=512, N=4096, K=512
    mm_h<<<gV, 256, SMEM_HALF * 2>>>(woh, C_, 0,  ot, C_, CB,
                                     nullptr, out, HW_, CB,
                                     bo, nullptr, q, CB,
                                     0.7071067811865476f, C_ / BK);
}

// round 4
// speedup vs baseline: 7.9714x; 1.0087x over previous
#include <cuda_runtime.h>
#include <cuda_fp16.h>
#include <cstdint>
#include <math.h>

// ---------------------------------------------------------------------------
// Attention2D (b=4, c=512, hw=4096) — Round 4.
//  - GEMMs: mma.sync m16n8k16 fp16/fp32, 3-stage cp.async ring, 1 sync/iter
//  - Softmax: MUFU-free (FMA poly exp2; log2e folded into scores alpha)
//  - Single weight-conversion kernel
// Layouts: every GEMM is D = A * B^T, K-major fp16 A and B.
// ---------------------------------------------------------------------------

#define B_  4
#define C_  512
#define HW_ 4096
#define NG_ 32
#define CPG_ (C_ / NG_)
#define GRP_ELEMS (CPG_ * HW_)

__device__ __align__(256) __half g_xt[(size_t)B_ * HW_ * C_];
__device__ __align__(256) __half g_qt[(size_t)B_ * HW_ * C_];
__device__ __align__(256) __half g_kt[(size_t)B_ * HW_ * C_];
__device__ __align__(256) __half g_v [(size_t)B_ * C_ * HW_];
__device__ __align__(256) __half g_st[(size_t)B_ * HW_ * HW_];
__device__ __align__(256) __half g_ot[(size_t)B_ * HW_ * C_];
__device__ __align__(256) __half g_wh[4][(size_t)C_ * C_];
__device__ float2 g_stats[B_ * NG_];

// ============================ small kernels ================================
// all four 512x512 weights -> fp16 in one launch (float4 vectorized)
__global__ __launch_bounds__(256) void f2h4_kernel(
    const float* __restrict__ w0, const float* __restrict__ w1,
    const float* __restrict__ w2, const float* __restrict__ w3,
    __half* __restrict__ o)
{
    const int n4 = C_ * C_ / 4;                 // 65536 float4 per weight
    int i = blockIdx.x * blockDim.x + threadIdx.x;  // 0 .. 4*n4-1
    int w = i >> 16;                             // which weight
    int e = i & (n4 - 1);
    const float* src = (w == 0) ? w0 : (w == 1) ? w1 : (w == 2) ? w2 : w3;
    float4 v = reinterpret_cast<const float4*>(src)[e];
    __half2 h0 = __floats2half2_rn(v.x, v.y);
    __half2 h1 = __floats2half2_rn(v.z, v.w);
    __half2* dst = reinterpret_cast<__half2*>(o + (size_t)w * C_ * C_);
    dst[2 * e] = h0;
    dst[2 * e + 1] = h1;
}

__global__ __launch_bounds__(256) void gn_stats(
    const float* __restrict__ x, float2* __restrict__ stats)
{
    int b = blockIdx.x / NG_, g = blockIdx.x % NG_;
    size_t base = ((size_t)b * C_ + (size_t)g * CPG_) * HW_;
    const float4* x4 = reinterpret_cast<const float4*>(x + base);
    int t = threadIdx.x;
    float s = 0.f, ss = 0.f;
    for (int i = t; i < GRP_ELEMS / 4; i += 256) {
        float4 v = x4[i];
        s  += v.x + v.y + v.z + v.w;
        ss += v.x * v.x + v.y * v.y + v.z * v.z + v.w * v.w;
    }
    __shared__ float rs[8], rss[8];
    #pragma unroll
    for (int o = 16; o; o >>= 1) {
        s  += __shfl_xor_sync(0xffffffffu, s,  o);
        ss += __shfl_xor_sync(0xffffffffu, ss, o);
    }
    if ((t & 31) == 0) { rs[t >> 5] = s; rss[t >> 5] = ss; }
    __syncthreads();
    if (t == 0) {
        float ts = 0.f, tss = 0.f;
        #pragma unroll
        for (int i = 0; i < 8; i++) { ts += rs[i]; tss += rss[i]; }
        float inv_n = 1.0f / (float)GRP_ELEMS;
        float mu = ts * inv_n;
        float var = tss * inv_n - mu * mu;
        stats[blockIdx.x] = make_float2(mu, rsqrtf(var + 1e-6f));
    }
}

__global__ __launch_bounds__(256) void gn_apply_t(
    const float* __restrict__ x, const float2* __restrict__ stats,
    const float* __restrict__ gamma, const float* __restrict__ beta,
    __half* __restrict__ xt)
{
    __shared__ float tile[32][33];
    int j0 = blockIdx.x * 32, c0 = blockIdx.y * 32, b = blockIdx.z;
    int tx = threadIdx.x & 31, ty = threadIdx.x >> 5;
    size_t xb = (size_t)b * C_ * HW_;
    #pragma unroll
    for (int it = 0; it < 4; it++) {
        int c = c0 + ty + it * 8;
        float v = x[xb + (size_t)c * HW_ + j0 + tx];
        float2 s = stats[b * NG_ + (c >> 4)];
        tile[ty + it * 8][tx] = (v - s.x) * s.y * gamma[c] + beta[c];
    }
    __syncthreads();
    size_t tb = (size_t)b * HW_ * C_;
    #pragma unroll
    for (int it = 0; it < 4; it++) {
        int j = j0 + ty + it * 8;
        xt[tb + (size_t)j * C_ + c0 + tx] = __float2half(tile[tx][ty + it * 8]);
    }
}

// ========================= fp16 mma.sync GEMM ==============================
#define BM 128
#define BN 128
#define BK 64
#define NSTAGE 3
#define STAGE_B (2 * BM * BK)          // bytes per stage per tensor (A or B)
#define SMEM_SZ (NSTAGE * 2 * STAGE_B) // 96 KB

__device__ __forceinline__ uint32_t smem_u32(const void* p) {
    uint32_t a;
    asm("{ .reg .u64 t; cvta.to.shared.u64 t, %1; cvt.u32.u64 %0, t; }"
        : "=r"(a) : "l"(p));
    return a;
}

__device__ __forceinline__ void load_tile_h(
    uint32_t sdst, const __half* __restrict__ src, long ld, int tid)
{
    #pragma unroll
    for (int i = 0; i < 4; i++) {
        int idx = tid + (i << 8);
        int r = idx >> 3;
        int c = idx & 7;
        uint32_t sw = (uint32_t)r * 128 + (uint32_t)((c ^ (r & 7)) << 4);
        asm volatile("cp.async.cg.shared.global [%0], [%1], 16;"
                     :: "r"(sdst + sw), "l"(src + (long)r * ld + (c << 3))
                     : "memory");
    }
}

#define LDSM4(r0, r1, r2, r3, a)                                           \
    asm volatile("ldmatrix.sync.aligned.m8n8.x4.shared.b16 {%0,%1,%2,%3}, [%4];" \
                 : "=r"(r0), "=r"(r1), "=r"(r2), "=r"(r3) : "r"(a))

__global__ __launch_bounds__(256) void mm_h(
    const __half* __restrict__ A, long lda, long asb,
    const __half* __restrict__ Bp, long ldb, long bsb,
    __half* __restrict__ Ch, float* __restrict__ Cf, long ldc, long csb,
    const float* __restrict__ bias_m, const float* __restrict__ bias_n,
    const float* __restrict__ res, long rsb, float alpha, int T)
{
    extern __shared__ __half smem[];
    uint32_t sb = smem_u32(smem);
    uint32_t sA[NSTAGE], sB[NSTAGE];
    #pragma unroll
    for (int s = 0; s < NSTAGE; s++) {
        sA[s] = sb + (uint32_t)s * 2 * STAGE_B;
        sB[s] = sA[s] + STAGE_B;
    }

    int tid = threadIdx.x, lane = tid & 31, wid = tid >> 5;
    int wm = wid >> 2, wn = wid & 3;
    int bz = blockIdx.z;
    int m0 = blockIdx.y * BM, n0 = blockIdx.x * BN;

    const __half* Ab = A  + (size_t)bz * asb + (size_t)m0 * lda;
    const __half* Bb = Bp + (size_t)bz * bsb + (size_t)n0 * ldb;

    float acc[4][4][4];
    #pragma unroll
    for (int i = 0; i < 4; i++)
        #pragma unroll
        for (int j = 0; j < 4; j++)
            #pragma unroll
            for (int k = 0; k < 4; k++) acc[i][j][k] = 0.f;

    int a_r  = (lane & 7) | (((lane >> 3) & 1) << 3);
    int a_cs = lane >> 4;
    int b_r  = (lane & 7) | (((lane >> 4) & 1) << 3);
    int b_cs = (lane >> 3) & 1;

    // prologue: stages 0 and 1 (2 commit groups)
    load_tile_h(sA[0], Ab, lda, tid);
    load_tile_h(sB[0], Bb, ldb, tid);
    asm volatile("cp.async.commit_group;");
    if (T > 1) {
        load_tile_h(sA[1], Ab + (size_t)BK, lda, tid);
        load_tile_h(sB[1], Bb + (size_t)BK, ldb, tid);
    }
    asm volatile("cp.async.commit_group;");

    for (int t = 0; t < T; t++) {
        int cs = t % NSTAGE;
        asm volatile("cp.async.wait_group 1;");
        __syncthreads();

        if (t + 2 < T) {
            int ns = (t + 2) % NSTAGE;
            load_tile_h(sA[ns], Ab + (size_t)(t + 2) * BK, lda, tid);
            load_tile_h(sB[ns], Bb + (size_t)(t + 2) * BK, ldb, tid);
        }
        asm volatile("cp.async.commit_group;");

        #pragma unroll
        for (int ks = 0; ks < 4; ks++) {
            uint32_t a[4][4], b[4][2];
            int ach = ks * 2 + a_cs;
            #pragma unroll
            for (int mt = 0; mt < 4; mt++) {
                int row = wm * 64 + mt * 16 + a_r;
                uint32_t addr = sA[cs] + (uint32_t)row * 128
                              + (uint32_t)((ach ^ (row & 7)) << 4);
                LDSM4(a[mt][0], a[mt][1], a[mt][2], a[mt][3], addr);
            }
            int bch = ks * 2 + b_cs;
            #pragma unroll
            for (int p = 0; p < 2; p++) {
                int row = wn * 32 + p * 16 + b_r;
                uint32_t addr = sB[cs] + (uint32_t)row * 128
                              + (uint32_t)((bch ^ (row & 7)) << 4);
                LDSM4(b[2 * p][0], b[2 * p][1], b[2 * p + 1][0], b[2 * p + 1][1], addr);
            }
            #pragma unroll
            for (int mt = 0; mt < 4; mt++)
                #pragma unroll
                for (int nt = 0; nt < 4; nt++)
                    asm volatile(
                        "mma.sync.aligned.m16n8k16.row.col.f32.f16.f16.f32 "
                        "{%0,%1,%2,%3}, {%4,%5,%6,%7}, {%8,%9}, {%0,%1,%2,%3};"
                        : "+f"(acc[mt][nt][0]), "+f"(acc[mt][nt][1]),
                          "+f"(acc[mt][nt][2]), "+f"(acc[mt][nt][3])
                        : "r"(a[mt][0]), "r"(a[mt][1]), "r"(a[mt][2]), "r"(a[mt][3]),
                          "r"(b[nt][0]), "r"(b[nt][1]));
        }
    }

    // ------------------------------ epilogue -------------------------------
    int mb = m0 + wm * 64;
    int nb = n0 + wn * 32;
    int r0 = lane >> 2, c0 = (lane & 3) * 2;
    __half* Chb = Ch ? Ch + (size_t)bz * csb : nullptr;
    float*  Cfb = Cf ? Cf + (size_t)bz * csb : nullptr;
    const float* Rb = res ? res + (size_t)bz * rsb : nullptr;

    #pragma unroll
    for (int mt = 0; mt < 4; mt++) {
        #pragma unroll
        for (int h = 0; h < 2; h++) {
            int m = mb + mt * 16 + r0 + h * 8;
            float bmv = bias_m ? bias_m[m] : 0.f;
            #pragma unroll
            for (int nt = 0; nt < 4; nt++) {
                int n = nb + nt * 8 + c0;
                float v0 = acc[mt][nt][2 * h + 0];
                float v1 = acc[mt][nt][2 * h + 1];
                v0 += bmv; v1 += bmv;
                if (bias_n) { v0 += bias_n[n]; v1 += bias_n[n + 1]; }
                if (Rb) {
                    const float* rp = Rb + (size_t)m * ldc + n;
                    v0 += rp[0]; v1 += rp[1];
                }
                v0 *= alpha; v1 *= alpha;
                if (Chb) {
                    *reinterpret_cast<__half2*>(Chb + (size_t)m * ldc + n) =
                        __floats2half2_rn(v0, v1);
                } else {
                    float2 f2 = make_float2(v0, v1);
                    *reinterpret_cast<float2*>(Cfb + (size_t)m * ldc + n) = f2;
                }
            }
        }
    }
}

// ===================== Softmax (MUFU-free, base-2) =========================
// Scores were scaled by scale*log2(e), so softmax = exp2(s - m) / sum.
__device__ __forceinline__ float fexp2(float x) {
    x = fmaxf(x, -120.f);
    float k = rintf(x);
    float r = x - k;
    float p = 0.0013333558f;
    p = fmaf(p, r, 0.0096181291f);
    p = fmaf(p, r, 0.0555041087f);
    p = fmaf(p, r, 0.2402265069f);
    p = fmaf(p, r, 0.6931471806f);
    p = fmaf(p, r, 1.0f);
    return p * __int_as_float(((int)k + 127) << 23);
}

__global__ __launch_bounds__(256) void softmax_h(__half* __restrict__ st)
{
    size_t row = ((size_t)blockIdx.y * HW_ + blockIdx.x) * HW_;
    // 4096 halves per row = 512 half2 = 128 uint4 per row; 256 thr * 2 uint4
    uint4* p = reinterpret_cast<uint4*>(st + row);
    int t = threadIdx.x;

    uint4 u[2];
    u[0] = p[t];
    u[1] = p[t + 256];
    float f[16];
    #pragma unroll
    for (int e = 0; e < 2; e++) {
        const uint32_t* w = &u[e].x;
        #pragma unroll
        for (int j = 0; j < 4; j++) {
            float2 v = __half22float2(*reinterpret_cast<const __half2*>(&w[j]));
            f[e * 8 + 2 * j]     = v.x;
            f[e * 8 + 2 * j + 1] = v.y;
        }
    }

    float mx = -1e30f;
    #pragma unroll
    for (int e = 0; e < 16; e++) mx = fmaxf(mx, f[e]);
    __shared__ float red[8];
    #pragma unroll
    for (int o = 16; o; o >>= 1) mx = fmaxf(mx, __shfl_xor_sync(0xffffffffu, mx, o));
    if ((t & 31) == 0) red[t >> 5] = mx;
    __syncthreads();
    float bmx = red[0];
    #pragma unroll
    for (int i = 1; i < 8; i++) bmx = fmaxf(bmx, red[i]);
    __syncthreads();

    float s = 0.f;
    #pragma unroll
    for (int e = 0; e < 16; e++) { f[e] = fexp2(f[e] - bmx); s += f[e]; }
    #pragma unroll
    for (int o = 16; o; o >>= 1) s += __shfl_xor_sync(0xffffffffu, s, o);
    if ((t & 31) == 0) red[t >> 5] = s;
    __syncthreads();
    float ts = 0.f;
    #pragma unroll
    for (int i = 0; i < 8; i++) ts += red[i];
    float inv = 1.0f / ts;

    #pragma unroll
    for (int e = 0; e < 2; e++) {
        uint32_t* w = &u[e].x;
        #pragma unroll
        for (int j = 0; j < 4; j++) {
            __half2 h = __floats2half2_rn(f[e * 8 + 2 * j] * inv,
                                          f[e * 8 + 2 * j + 1] * inv);
            w[j] = *reinterpret_cast<uint32_t*>(&h);
        }
    }
    p[t]       = u[0];
    p[t + 256] = u[1];
}

// ============================ Launcher =====================================
extern "C" void kernel_launch(void* const* d_in, const int* in_sizes, int n_in,
                              void* d_out, int out_size)
{
    const float* q     = (const float*)d_in[0];
    const float* gamma = (const float*)d_in[1];
    const float* beta  = (const float*)d_in[2];
    const float* wq    = (const float*)d_in[3];
    const float* bq    = (const float*)d_in[4];
    const float* wk    = (const float*)d_in[5];
    const float* bk    = (const float*)d_in[6];
    const float* wv    = (const float*)d_in[7];
    const float* bv    = (const float*)d_in[8];
    const float* wo    = (const float*)d_in[9];
    const float* bo    = (const float*)d_in[10];
    float* out = (float*)d_out;

    __half *xt, *qt, *kt, *v, *st, *ot, *wh;
    float2* stats;
    cudaGetSymbolAddress((void**)&xt, g_xt);
    cudaGetSymbolAddress((void**)&qt, g_qt);
    cudaGetSymbolAddress((void**)&kt, g_kt);
    cudaGetSymbolAddress((void**)&v,  g_v);
    cudaGetSymbolAddress((void**)&st, g_st);
    cudaGetSymbolAddress((void**)&ot, g_ot);
    cudaGetSymbolAddress((void**)&wh, g_wh);
    cudaGetSymbolAddress((void**)&stats, g_stats);
    __half* wqh = wh;
    __half* wkh = wh + (size_t)C_ * C_;
    __half* wvh = wh + 2 * (size_t)C_ * C_;
    __half* woh = wh + 3 * (size_t)C_ * C_;

    static int smem_set = 0;
    if (!smem_set) {
        cudaFuncSetAttribute(mm_h, cudaFuncAttributeMaxDynamicSharedMemorySize,
                             SMEM_SZ);
        smem_set = 1;
    }

    const long CB = (long)C_ * HW_;
    const long SB = (long)HW_ * HW_;

    // 0. weights -> fp16 (single launch)
    f2h4_kernel<<<(4 * C_ * C_ / 4) / 256, 256>>>(wq, wk, wv, wo, wh);

    // 1. GroupNorm -> Xt[j][c] fp16
    gn_stats<<<B_ * NG_, 256>>>(q, stats);
    gn_apply_t<<<dim3(HW_ / 32, C_ / 32, B_), 256>>>(q, stats, gamma, beta, xt);

    // 2. Qt / Kt: M=4096(j), N=512(c), K=512
    dim3 gP(C_ / BN, HW_ / BM, B_);
    mm_h<<<gP, 256, SMEM_SZ>>>(xt, C_, CB,  wqh, C_, 0,
                               qt, nullptr, C_, CB,
                               nullptr, bq, nullptr, 0, 1.0f, C_ / BK);
    mm_h<<<gP, 256, SMEM_SZ>>>(xt, C_, CB,  wkh, C_, 0,
                               kt, nullptr, C_, CB,
                               nullptr, bk, nullptr, 0, 1.0f, C_ / BK);

    // 3. V[c][i]: M=512(c), N=4096(i), K=512
    dim3 gV(HW_ / BN, C_ / BM, B_);
    mm_h<<<gV, 256, SMEM_SZ>>>(wvh, C_, 0,  xt, C_, CB,
                               v, nullptr, HW_, CB,
                               bv, nullptr, nullptr, 0, 1.0f, C_ / BK);

    // 4. ST[j][i] = (scale*log2e) * Qt @ Kt^T: M=N=4096, K=512
    dim3 gS(HW_ / BN, HW_ / BM, B_);
    mm_h<<<gS, 256, SMEM_SZ>>>(qt, C_, CB,  kt, C_, CB,
                               st, nullptr, HW_, SB,
                               nullptr, nullptr, nullptr, 0,
                               0.044194173824159216f * 1.4426950408889634f,
                               C_ / BK);

    // 5. softmax over i (base-2 domain)
    softmax_h<<<dim3(HW_, B_), 256>>>(st);

    // 6. Ot[j][c] = ST @ V^T: M=4096(j), N=512(c), K=4096
    mm_h<<<gP, 256, SMEM_SZ>>>(st, HW_, SB,  v, HW_, CB,
                               ot, nullptr, C_, CB,
                               nullptr, nullptr, nullptr, 0, 1.0f, HW_ / BK);

    // 7. out[c][j] = (Wo @ Ot^T + bo + q) * inv_sqrt2: M=512, N=4096, K=512
    mm_h<<<gV, 256, SMEM_SZ>>>(woh, C_, 0,  ot, C_, CB,
                               nullptr, out, HW_, CB,
                               bo, nullptr, q, CB,
                               0.7071067811865476f, C_ / BK);
}

// round 5
// speedup vs baseline: 9.2061x; 1.1549x over previous
#include <cuda_runtime.h>
#include <cuda_fp16.h>
#include <cstdint>
#include <math.h>

// ---------------------------------------------------------------------------
// Attention2D (b=4, c=512, hw=4096) — Round 5.
// Change vs R4: mm_h __launch_bounds__(256, 2) -> 2 CTAs/SM (regs <= 128),
// 4 warps/scheduler to keep the HMMA pipe fed.
// ---------------------------------------------------------------------------

#define B_  4
#define C_  512
#define HW_ 4096
#define NG_ 32
#define CPG_ (C_ / NG_)
#define GRP_ELEMS (CPG_ * HW_)

__device__ __align__(256) __half g_xt[(size_t)B_ * HW_ * C_];
__device__ __align__(256) __half g_qt[(size_t)B_ * HW_ * C_];
__device__ __align__(256) __half g_kt[(size_t)B_ * HW_ * C_];
__device__ __align__(256) __half g_v [(size_t)B_ * C_ * HW_];
__device__ __align__(256) __half g_st[(size_t)B_ * HW_ * HW_];
__device__ __align__(256) __half g_ot[(size_t)B_ * HW_ * C_];
__device__ __align__(256) __half g_wh[4][(size_t)C_ * C_];
__device__ float2 g_stats[B_ * NG_];

// ============================ small kernels ================================
__global__ __launch_bounds__(256) void f2h4_kernel(
    const float* __restrict__ w0, const float* __restrict__ w1,
    const float* __restrict__ w2, const float* __restrict__ w3,
    __half* __restrict__ o)
{
    const int n4 = C_ * C_ / 4;
    int i = blockIdx.x * blockDim.x + threadIdx.x;
    int w = i >> 16;
    int e = i & (n4 - 1);
    const float* src = (w == 0) ? w0 : (w == 1) ? w1 : (w == 2) ? w2 : w3;
    float4 v = reinterpret_cast<const float4*>(src)[e];
    __half2 h0 = __floats2half2_rn(v.x, v.y);
    __half2 h1 = __floats2half2_rn(v.z, v.w);
    __half2* dst = reinterpret_cast<__half2*>(o + (size_t)w * C_ * C_);
    dst[2 * e] = h0;
    dst[2 * e + 1] = h1;
}

__global__ __launch_bounds__(256) void gn_stats(
    const float* __restrict__ x, float2* __restrict__ stats)
{
    int b = blockIdx.x / NG_, g = blockIdx.x % NG_;
    size_t base = ((size_t)b * C_ + (size_t)g * CPG_) * HW_;
    const float4* x4 = reinterpret_cast<const float4*>(x + base);
    int t = threadIdx.x;
    float s = 0.f, ss = 0.f;
    for (int i = t; i < GRP_ELEMS / 4; i += 256) {
        float4 v = x4[i];
        s  += v.x + v.y + v.z + v.w;
        ss += v.x * v.x + v.y * v.y + v.z * v.z + v.w * v.w;
    }
    __shared__ float rs[8], rss[8];
    #pragma unroll
    for (int o = 16; o; o >>= 1) {
        s  += __shfl_xor_sync(0xffffffffu, s,  o);
        ss += __shfl_xor_sync(0xffffffffu, ss, o);
    }
    if ((t & 31) == 0) { rs[t >> 5] = s; rss[t >> 5] = ss; }
    __syncthreads();
    if (t == 0) {
        float ts = 0.f, tss = 0.f;
        #pragma unroll
        for (int i = 0; i < 8; i++) { ts += rs[i]; tss += rss[i]; }
        float inv_n = 1.0f / (float)GRP_ELEMS;
        float mu = ts * inv_n;
        float var = tss * inv_n - mu * mu;
        stats[blockIdx.x] = make_float2(mu, rsqrtf(var + 1e-6f));
    }
}

__global__ __launch_bounds__(256) void gn_apply_t(
    const float* __restrict__ x, const float2* __restrict__ stats,
    const float* __restrict__ gamma, const float* __restrict__ beta,
    __half* __restrict__ xt)
{
    __shared__ float tile[32][33];
    int j0 = blockIdx.x * 32, c0 = blockIdx.y * 32, b = blockIdx.z;
    int tx = threadIdx.x & 31, ty = threadIdx.x >> 5;
    size_t xb = (size_t)b * C_ * HW_;
    #pragma unroll
    for (int it = 0; it < 4; it++) {
        int c = c0 + ty + it * 8;
        float v = x[xb + (size_t)c * HW_ + j0 + tx];
        float2 s = stats[b * NG_ + (c >> 4)];
        tile[ty + it * 8][tx] = (v - s.x) * s.y * gamma[c] + beta[c];
    }
    __syncthreads();
    size_t tb = (size_t)b * HW_ * C_;
    #pragma unroll
    for (int it = 0; it < 4; it++) {
        int j = j0 + ty + it * 8;
        xt[tb + (size_t)j * C_ + c0 + tx] = __float2half(tile[tx][ty + it * 8]);
    }
}

// ========================= fp16 mma.sync GEMM ==============================
#define BM 128
#define BN 128
#define BK 64
#define NSTAGE 3
#define STAGE_B (2 * BM * BK)
#define SMEM_SZ (NSTAGE * 2 * STAGE_B)   // 96 KB

__device__ __forceinline__ uint32_t smem_u32(const void* p) {
    uint32_t a;
    asm("{ .reg .u64 t; cvta.to.shared.u64 t, %1; cvt.u32.u64 %0, t; }"
        : "=r"(a) : "l"(p));
    return a;
}

__device__ __forceinline__ void load_tile_h(
    uint32_t sdst, const __half* __restrict__ src, long ld, int tid)
{
    #pragma unroll
    for (int i = 0; i < 4; i++) {
        int idx = tid + (i << 8);
        int r = idx >> 3;
        int c = idx & 7;
        uint32_t sw = (uint32_t)r * 128 + (uint32_t)((c ^ (r & 7)) << 4);
        asm volatile("cp.async.cg.shared.global [%0], [%1], 16;"
                     :: "r"(sdst + sw), "l"(src + (long)r * ld + (c << 3))
                     : "memory");
    }
}

#define LDSM4(r0, r1, r2, r3, a)                                           \
    asm volatile("ldmatrix.sync.aligned.m8n8.x4.shared.b16 {%0,%1,%2,%3}, [%4];" \
                 : "=r"(r0), "=r"(r1), "=r"(r2), "=r"(r3) : "r"(a))

__global__ __launch_bounds__(256, 2) void mm_h(
    const __half* __restrict__ A, long lda, long asb,
    const __half* __restrict__ Bp, long ldb, long bsb,
    __half* __restrict__ Ch, float* __restrict__ Cf, long ldc, long csb,
    const float* __restrict__ bias_m, const float* __restrict__ bias_n,
    const float* __restrict__ res, long rsb, float alpha, int T)
{
    extern __shared__ __half smem[];
    uint32_t sb = smem_u32(smem);
    uint32_t sA[NSTAGE], sB[NSTAGE];
    #pragma unroll
    for (int s = 0; s < NSTAGE; s++) {
        sA[s] = sb + (uint32_t)s * 2 * STAGE_B;
        sB[s] = sA[s] + STAGE_B;
    }

    int tid = threadIdx.x, lane = tid & 31, wid = tid >> 5;
    int wm = wid >> 2, wn = wid & 3;
    int bz = blockIdx.z;
    int m0 = blockIdx.y * BM, n0 = blockIdx.x * BN;

    const __half* Ab = A  + (size_t)bz * asb + (size_t)m0 * lda;
    const __half* Bb = Bp + (size_t)bz * bsb + (size_t)n0 * ldb;

    float acc[4][4][4];
    #pragma unroll
    for (int i = 0; i < 4; i++)
        #pragma unroll
        for (int j = 0; j < 4; j++)
            #pragma unroll
            for (int k = 0; k < 4; k++) acc[i][j][k] = 0.f;

    int a_r  = (lane & 7) | (((lane >> 3) & 1) << 3);
    int a_cs = lane >> 4;
    int b_r  = (lane & 7) | (((lane >> 4) & 1) << 3);
    int b_cs = (lane >> 3) & 1;

    load_tile_h(sA[0], Ab, lda, tid);
    load_tile_h(sB[0], Bb, ldb, tid);
    asm volatile("cp.async.commit_group;");
    if (T > 1) {
        load_tile_h(sA[1], Ab + (size_t)BK, lda, tid);
        load_tile_h(sB[1], Bb + (size_t)BK, ldb, tid);
    }
    asm volatile("cp.async.commit_group;");

    for (int t = 0; t < T; t++) {
        int cs = t % NSTAGE;
        asm volatile("cp.async.wait_group 1;");
        __syncthreads();

        if (t + 2 < T) {
            int ns = (t + 2) % NSTAGE;
            load_tile_h(sA[ns], Ab + (size_t)(t + 2) * BK, lda, tid);
            load_tile_h(sB[ns], Bb + (size_t)(t + 2) * BK, ldb, tid);
        }
        asm volatile("cp.async.commit_group;");

        #pragma unroll
        for (int ks = 0; ks < 4; ks++) {
            uint32_t a[4][4], b[4][2];
            int ach = ks * 2 + a_cs;
            #pragma unroll
            for (int mt = 0; mt < 4; mt++) {
                int row = wm * 64 + mt * 16 + a_r;
                uint32_t addr = sA[cs] + (uint32_t)row * 128
                              + (uint32_t)((ach ^ (row & 7)) << 4);
                LDSM4(a[mt][0], a[mt][1], a[mt][2], a[mt][3], addr);
            }
            int bch = ks * 2 + b_cs;
            #pragma unroll
            for (int p = 0; p < 2; p++) {
                int row = wn * 32 + p * 16 + b_r;
                uint32_t addr = sB[cs] + (uint32_t)row * 128
                              + (uint32_t)((bch ^ (row & 7)) << 4);
                LDSM4(b[2 * p][0], b[2 * p][1], b[2 * p + 1][0], b[2 * p + 1][1], addr);
            }
            #pragma unroll
            for (int mt = 0; mt < 4; mt++)
                #pragma unroll
                for (int nt = 0; nt < 4; nt++)
                    asm volatile(
                        "mma.sync.aligned.m16n8k16.row.col.f32.f16.f16.f32 "
                        "{%0,%1,%2,%3}, {%4,%5,%6,%7}, {%8,%9}, {%0,%1,%2,%3};"
                        : "+f"(acc[mt][nt][0]), "+f"(acc[mt][nt][1]),
                          "+f"(acc[mt][nt][2]), "+f"(acc[mt][nt][3])
                        : "r"(a[mt][0]), "r"(a[mt][1]), "r"(a[mt][2]), "r"(a[mt][3]),
                          "r"(b[nt][0]), "r"(b[nt][1]));
        }
    }

    // ------------------------------ epilogue -------------------------------
    int mb = m0 + wm * 64;
    int nb = n0 + wn * 32;
    int r0 = lane >> 2, c0 = (lane & 3) * 2;
    __half* Chb = Ch ? Ch + (size_t)bz * csb : nullptr;
    float*  Cfb = Cf ? Cf + (size_t)bz * csb : nullptr;
    const float* Rb = res ? res + (size_t)bz * rsb : nullptr;

    #pragma unroll
    for (int mt = 0; mt < 4; mt++) {
        #pragma unroll
        for (int h = 0; h < 2; h++) {
            int m = mb + mt * 16 + r0 + h * 8;
            float bmv = bias_m ? bias_m[m] : 0.f;
            #pragma unroll
            for (int nt = 0; nt < 4; nt++) {
                int n = nb + nt * 8 + c0;
                float v0 = acc[mt][nt][2 * h + 0];
                float v1 = acc[mt][nt][2 * h + 1];
                v0 += bmv; v1 += bmv;
                if (bias_n) { v0 += bias_n[n]; v1 += bias_n[n + 1]; }
                if (Rb) {
                    const float* rp = Rb + (size_t)m * ldc + n;
                    v0 += rp[0]; v1 += rp[1];
                }
                v0 *= alpha; v1 *= alpha;
                if (Chb) {
                    *reinterpret_cast<__half2*>(Chb + (size_t)m * ldc + n) =
                        __floats2half2_rn(v0, v1);
                } else {
                    float2 f2 = make_float2(v0, v1);
                    *reinterpret_cast<float2*>(Cfb + (size_t)m * ldc + n) = f2;
                }
            }
        }
    }
}

// ===================== Softmax (MUFU-free, base-2) =========================
__device__ __forceinline__ float fexp2(float x) {
    x = fmaxf(x, -120.f);
    float k = rintf(x);
    float r = x - k;
    float p = 0.0013333558f;
    p = fmaf(p, r, 0.0096181291f);
    p = fmaf(p, r, 0.0555041087f);
    p = fmaf(p, r, 0.2402265069f);
    p = fmaf(p, r, 0.6931471806f);
    p = fmaf(p, r, 1.0f);
    return p * __int_as_float(((int)k + 127) << 23);
}

__global__ __launch_bounds__(256) void softmax_h(__half* __restrict__ st)
{
    size_t row = ((size_t)blockIdx.y * HW_ + blockIdx.x) * HW_;
    uint4* p = reinterpret_cast<uint4*>(st + row);
    int t = threadIdx.x;

    uint4 u[2];
    u[0] = p[t];
    u[1] = p[t + 256];
    float f[16];
    #pragma unroll
    for (int e = 0; e < 2; e++) {
        const uint32_t* w = &u[e].x;
        #pragma unroll
        for (int j = 0; j < 4; j++) {
            float2 v = __half22float2(*reinterpret_cast<const __half2*>(&w[j]));
            f[e * 8 + 2 * j]     = v.x;
            f[e * 8 + 2 * j + 1] = v.y;
        }
    }

    float mx = -1e30f;
    #pragma unroll
    for (int e = 0; e < 16; e++) mx = fmaxf(mx, f[e]);
    __shared__ float red[8];
    #pragma unroll
    for (int o = 16; o; o >>= 1) mx = fmaxf(mx, __shfl_xor_sync(0xffffffffu, mx, o));
    if ((t & 31) == 0) red[t >> 5] = mx;
    __syncthreads();
    float bmx = red[0];
    #pragma unroll
    for (int i = 1; i < 8; i++) bmx = fmaxf(bmx, red[i]);
    __syncthreads();

    float s = 0.f;
    #pragma unroll
    for (int e = 0; e < 16; e++) { f[e] = fexp2(f[e] - bmx); s += f[e]; }
    #pragma unroll
    for (int o = 16; o; o >>= 1) s += __shfl_xor_sync(0xffffffffu, s, o);
    if ((t & 31) == 0) red[t >> 5] = s;
    __syncthreads();
    float ts = 0.f;
    #pragma unroll
    for (int i = 0; i < 8; i++) ts += red[i];
    float inv = 1.0f / ts;

    #pragma unroll
    for (int e = 0; e < 2; e++) {
        uint32_t* w = &u[e].x;
        #pragma unroll
        for (int j = 0; j < 4; j++) {
            __half2 h = __floats2half2_rn(f[e * 8 + 2 * j] * inv,
                                          f[e * 8 + 2 * j + 1] * inv);
            w[j] = *reinterpret_cast<uint32_t*>(&h);
        }
    }
    p[t]       = u[0];
    p[t + 256] = u[1];
}

// ============================ Launcher =====================================
extern "C" void kernel_launch(void* const* d_in, const int* in_sizes, int n_in,
                              void* d_out, int out_size)
{
    const float* q     = (const float*)d_in[0];
    const float* gamma = (const float*)d_in[1];
    const float* beta  = (const float*)d_in[2];
    const float* wq    = (const float*)d_in[3];
    const float* bq    = (const float*)d_in[4];
    const float* wk    = (const float*)d_in[5];
    const float* bk    = (const float*)d_in[6];
    const float* wv    = (const float*)d_in[7];
    const float* bv    = (const float*)d_in[8];
    const float* wo    = (const float*)d_in[9];
    const float* bo    = (const float*)d_in[10];
    float* out = (float*)d_out;

    __half *xt, *qt, *kt, *v, *st, *ot, *wh;
    float2* stats;
    cudaGetSymbolAddress((void**)&xt, g_xt);
    cudaGetSymbolAddress((void**)&qt, g_qt);
    cudaGetSymbolAddress((void**)&kt, g_kt);
    cudaGetSymbolAddress((void**)&v,  g_v);
    cudaGetSymbolAddress((void**)&st, g_st);
    cudaGetSymbolAddress((void**)&ot, g_ot);
    cudaGetSymbolAddress((void**)&wh, g_wh);
    cudaGetSymbolAddress((void**)&stats, g_stats);
    __half* wqh = wh;
    __half* wkh = wh + (size_t)C_ * C_;
    __half* wvh = wh + 2 * (size_t)C_ * C_;
    __half* woh = wh + 3 * (size_t)C_ * C_;

    static int smem_set = 0;
    if (!smem_set) {
        cudaFuncSetAttribute(mm_h, cudaFuncAttributeMaxDynamicSharedMemorySize,
                             SMEM_SZ);
        smem_set = 1;
    }

    const long CB = (long)C_ * HW_;
    const long SB = (long)HW_ * HW_;

    f2h4_kernel<<<(4 * C_ * C_ / 4) / 256, 256>>>(wq, wk, wv, wo, wh);

    gn_stats<<<B_ * NG_, 256>>>(q, stats);
    gn_apply_t<<<dim3(HW_ / 32, C_ / 32, B_), 256>>>(q, stats, gamma, beta, xt);

    dim3 gP(C_ / BN, HW_ / BM, B_);
    mm_h<<<gP, 256, SMEM_SZ>>>(xt, C_, CB,  wqh, C_, 0,
                               qt, nullptr, C_, CB,
                               nullptr, bq, nullptr, 0, 1.0f, C_ / BK);
    mm_h<<<gP, 256, SMEM_SZ>>>(xt, C_, CB,  wkh, C_, 0,
                               kt, nullptr, C_, CB,
                               nullptr, bk, nullptr, 0, 1.0f, C_ / BK);

    dim3 gV(HW_ / BN, C_ / BM, B_);
    mm_h<<<gV, 256, SMEM_SZ>>>(wvh, C_, 0,  xt, C_, CB,
                               v, nullptr, HW_, CB,
                               bv, nullptr, nullptr, 0, 1.0f, C_ / BK);

    dim3 gS(HW_ / BN, HW_ / BM, B_);
    mm_h<<<gS, 256, SMEM_SZ>>>(qt, C_, CB,  kt, C_, CB,
                               st, nullptr, HW_, SB,
                               nullptr, nullptr, nullptr, 0,
                               0.044194173824159216f * 1.4426950408889634f,
                               C_ / BK);

    softmax_h<<<dim3(HW_, B_), 256>>>(st);

    mm_h<<<gP, 256, SMEM_SZ>>>(st, HW_, SB,  v, HW_, CB,
                               ot, nullptr, C_, CB,
                               nullptr, nullptr, nullptr, 0, 1.0f, HW_ / BK);

    mm_h<<<gV, 256, SMEM_SZ>>>(woh, C_, 0,  ot, C_, CB,
                               nullptr, out, HW_, CB,
                               bo, nullptr, q, CB,
                               0.7071067811865476f, C_ / BK);
}

// round 6
// speedup vs baseline: 9.6686x; 1.0502x over previous
#include <cuda_runtime.h>
#include <cuda_fp16.h>
#include <cstdint>
#include <math.h>

// ---------------------------------------------------------------------------
// Attention2D (b=4, c=512, hw=4096) — Round 6.
// GEMM: 128x128 CTA tile, 128 threads, 2x2 warp grid, 64x64 warp tiles
// (halves LDSM redundancy vs R5's 2x4/64x32), 3-stage cp.async, 2 CTAs/SM.
// ---------------------------------------------------------------------------

#define B_  4
#define C_  512
#define HW_ 4096
#define NG_ 32
#define CPG_ (C_ / NG_)
#define GRP_ELEMS (CPG_ * HW_)

__device__ __align__(256) __half g_xt[(size_t)B_ * HW_ * C_];
__device__ __align__(256) __half g_qt[(size_t)B_ * HW_ * C_];
__device__ __align__(256) __half g_kt[(size_t)B_ * HW_ * C_];
__device__ __align__(256) __half g_v [(size_t)B_ * C_ * HW_];
__device__ __align__(256) __half g_st[(size_t)B_ * HW_ * HW_];
__device__ __align__(256) __half g_ot[(size_t)B_ * HW_ * C_];
__device__ __align__(256) __half g_wh[4][(size_t)C_ * C_];
__device__ float2 g_stats[B_ * NG_];

// ============================ small kernels ================================
__global__ __launch_bounds__(256) void f2h4_kernel(
    const float* __restrict__ w0, const float* __restrict__ w1,
    const float* __restrict__ w2, const float* __restrict__ w3,
    __half* __restrict__ o)
{
    const int n4 = C_ * C_ / 4;
    int i = blockIdx.x * blockDim.x + threadIdx.x;
    int w = i >> 16;
    int e = i & (n4 - 1);
    const float* src = (w == 0) ? w0 : (w == 1) ? w1 : (w == 2) ? w2 : w3;
    float4 v = reinterpret_cast<const float4*>(src)[e];
    __half2 h0 = __floats2half2_rn(v.x, v.y);
    __half2 h1 = __floats2half2_rn(v.z, v.w);
    __half2* dst = reinterpret_cast<__half2*>(o + (size_t)w * C_ * C_);
    dst[2 * e] = h0;
    dst[2 * e + 1] = h1;
}

__global__ __launch_bounds__(256) void gn_stats(
    const float* __restrict__ x, float2* __restrict__ stats)
{
    int b = blockIdx.x / NG_, g = blockIdx.x % NG_;
    size_t base = ((size_t)b * C_ + (size_t)g * CPG_) * HW_;
    const float4* x4 = reinterpret_cast<const float4*>(x + base);
    int t = threadIdx.x;
    float s = 0.f, ss = 0.f;
    for (int i = t; i < GRP_ELEMS / 4; i += 256) {
        float4 v = x4[i];
        s  += v.x + v.y + v.z + v.w;
        ss += v.x * v.x + v.y * v.y + v.z * v.z + v.w * v.w;
    }
    __shared__ float rs[8], rss[8];
    #pragma unroll
    for (int o = 16; o; o >>= 1) {
        s  += __shfl_xor_sync(0xffffffffu, s,  o);
        ss += __shfl_xor_sync(0xffffffffu, ss, o);
    }
    if ((t & 31) == 0) { rs[t >> 5] = s; rss[t >> 5] = ss; }
    __syncthreads();
    if (t == 0) {
        float ts = 0.f, tss = 0.f;
        #pragma unroll
        for (int i = 0; i < 8; i++) { ts += rs[i]; tss += rss[i]; }
        float inv_n = 1.0f / (float)GRP_ELEMS;
        float mu = ts * inv_n;
        float var = tss * inv_n - mu * mu;
        stats[blockIdx.x] = make_float2(mu, rsqrtf(var + 1e-6f));
    }
}

__global__ __launch_bounds__(256) void gn_apply_t(
    const float* __restrict__ x, const float2* __restrict__ stats,
    const float* __restrict__ gamma, const float* __restrict__ beta,
    __half* __restrict__ xt)
{
    __shared__ float tile[32][33];
    int j0 = blockIdx.x * 32, c0 = blockIdx.y * 32, b = blockIdx.z;
    int tx = threadIdx.x & 31, ty = threadIdx.x >> 5;
    size_t xb = (size_t)b * C_ * HW_;
    #pragma unroll
    for (int it = 0; it < 4; it++) {
        int c = c0 + ty + it * 8;
        float v = x[xb + (size_t)c * HW_ + j0 + tx];
        float2 s = stats[b * NG_ + (c >> 4)];
        tile[ty + it * 8][tx] = (v - s.x) * s.y * gamma[c] + beta[c];
    }
    __syncthreads();
    size_t tb = (size_t)b * HW_ * C_;
    #pragma unroll
    for (int it = 0; it < 4; it++) {
        int j = j0 + ty + it * 8;
        xt[tb + (size_t)j * C_ + c0 + tx] = __float2half(tile[tx][ty + it * 8]);
    }
}

// ========================= fp16 mma.sync GEMM ==============================
#define BM 128
#define BN 128
#define BK 64
#define NSTAGE 3
#define STAGE_B (2 * BM * BK)
#define SMEM_SZ (NSTAGE * 2 * STAGE_B)   // 96 KB

__device__ __forceinline__ uint32_t smem_u32(const void* p) {
    uint32_t a;
    asm("{ .reg .u64 t; cvta.to.shared.u64 t, %1; cvt.u32.u64 %0, t; }"
        : "=r"(a) : "l"(p));
    return a;
}

// load one 128x64-half tile with 128 threads (8 x 16B swizzled chunks / row)
__device__ __forceinline__ void load_tile_h(
    uint32_t sdst, const __half* __restrict__ src, long ld, int tid)
{
    #pragma unroll
    for (int i = 0; i < 8; i++) {
        int idx = tid + (i << 7);
        int r = idx >> 3;
        int c = idx & 7;
        uint32_t sw = (uint32_t)r * 128 + (uint32_t)((c ^ (r & 7)) << 4);
        asm volatile("cp.async.cg.shared.global [%0], [%1], 16;"
                     :: "r"(sdst + sw), "l"(src + (long)r * ld + (c << 3))
                     : "memory");
    }
}

#define LDSM4(r0, r1, r2, r3, a)                                           \
    asm volatile("ldmatrix.sync.aligned.m8n8.x4.shared.b16 {%0,%1,%2,%3}, [%4];" \
                 : "=r"(r0), "=r"(r1), "=r"(r2), "=r"(r3) : "r"(a))

__global__ __launch_bounds__(128, 2) void mm_h(
    const __half* __restrict__ A, long lda, long asb,
    const __half* __restrict__ Bp, long ldb, long bsb,
    __half* __restrict__ Ch, float* __restrict__ Cf, long ldc, long csb,
    const float* __restrict__ bias_m, const float* __restrict__ bias_n,
    const float* __restrict__ res, long rsb, float alpha, int T)
{
    extern __shared__ __half smem[];
    uint32_t sb = smem_u32(smem);
    uint32_t sA[NSTAGE], sB[NSTAGE];
    #pragma unroll
    for (int s = 0; s < NSTAGE; s++) {
        sA[s] = sb + (uint32_t)s * 2 * STAGE_B;
        sB[s] = sA[s] + STAGE_B;
    }

    int tid = threadIdx.x, lane = tid & 31, wid = tid >> 5;
    int wm = wid >> 1, wn = wid & 1;        // 2 x 2 warp grid, 64x64 tiles
    int bz = blockIdx.z;
    int m0 = blockIdx.y * BM, n0 = blockIdx.x * BN;

    const __half* Ab = A  + (size_t)bz * asb + (size_t)m0 * lda;
    const __half* Bb = Bp + (size_t)bz * bsb + (size_t)n0 * ldb;

    float acc[4][8][4];
    #pragma unroll
    for (int i = 0; i < 4; i++)
        #pragma unroll
        for (int j = 0; j < 8; j++)
            #pragma unroll
            for (int k = 0; k < 4; k++) acc[i][j][k] = 0.f;

    int a_r  = (lane & 7) | (((lane >> 3) & 1) << 3);
    int a_cs = lane >> 4;
    int b_r  = (lane & 7) | (((lane >> 4) & 1) << 3);
    int b_cs = (lane >> 3) & 1;

    load_tile_h(sA[0], Ab, lda, tid);
    load_tile_h(sB[0], Bb, ldb, tid);
    asm volatile("cp.async.commit_group;");
    if (T > 1) {
        load_tile_h(sA[1], Ab + (size_t)BK, lda, tid);
        load_tile_h(sB[1], Bb + (size_t)BK, ldb, tid);
    }
    asm volatile("cp.async.commit_group;");

    for (int t = 0; t < T; t++) {
        int cs = t % NSTAGE;
        asm volatile("cp.async.wait_group 1;");
        __syncthreads();

        if (t + 2 < T) {
            int ns = (t + 2) % NSTAGE;
            load_tile_h(sA[ns], Ab + (size_t)(t + 2) * BK, lda, tid);
            load_tile_h(sB[ns], Bb + (size_t)(t + 2) * BK, ldb, tid);
        }
        asm volatile("cp.async.commit_group;");

        #pragma unroll
        for (int ks = 0; ks < 4; ks++) {
            uint32_t a[4][4], b[8][2];
            int ach = ks * 2 + a_cs;
            #pragma unroll
            for (int mt = 0; mt < 4; mt++) {
                int row = wm * 64 + mt * 16 + a_r;
                uint32_t addr = sA[cs] + (uint32_t)row * 128
                              + (uint32_t)((ach ^ (row & 7)) << 4);
                LDSM4(a[mt][0], a[mt][1], a[mt][2], a[mt][3], addr);
            }
            int bch = ks * 2 + b_cs;
            #pragma unroll
            for (int p = 0; p < 4; p++) {
                int row = wn * 64 + p * 16 + b_r;
                uint32_t addr = sB[cs] + (uint32_t)row * 128
                              + (uint32_t)((bch ^ (row & 7)) << 4);
                LDSM4(b[2 * p][0], b[2 * p][1], b[2 * p + 1][0], b[2 * p + 1][1], addr);
            }
            #pragma unroll
            for (int mt = 0; mt < 4; mt++)
                #pragma unroll
                for (int nt = 0; nt < 8; nt++)
                    asm volatile(
                        "mma.sync.aligned.m16n8k16.row.col.f32.f16.f16.f32 "
                        "{%0,%1,%2,%3}, {%4,%5,%6,%7}, {%8,%9}, {%0,%1,%2,%3};"
                        : "+f"(acc[mt][nt][0]), "+f"(acc[mt][nt][1]),
                          "+f"(acc[mt][nt][2]), "+f"(acc[mt][nt][3])
                        : "r"(a[mt][0]), "r"(a[mt][1]), "r"(a[mt][2]), "r"(a[mt][3]),
                          "r"(b[nt][0]), "r"(b[nt][1]));
        }
    }

    // ------------------------------ epilogue -------------------------------
    int mb = m0 + wm * 64;
    int nb = n0 + wn * 64;
    int r0 = lane >> 2, c0 = (lane & 3) * 2;
    __half* Chb = Ch ? Ch + (size_t)bz * csb : nullptr;
    float*  Cfb = Cf ? Cf + (size_t)bz * csb : nullptr;
    const float* Rb = res ? res + (size_t)bz * rsb : nullptr;

    #pragma unroll
    for (int mt = 0; mt < 4; mt++) {
        #pragma unroll
        for (int h = 0; h < 2; h++) {
            int m = mb + mt * 16 + r0 + h * 8;
            float bmv = bias_m ? bias_m[m] : 0.f;
            #pragma unroll
            for (int nt = 0; nt < 8; nt++) {
                int n = nb + nt * 8 + c0;
                float v0 = acc[mt][nt][2 * h + 0];
                float v1 = acc[mt][nt][2 * h + 1];
                v0 += bmv; v1 += bmv;
                if (bias_n) { v0 += bias_n[n]; v1 += bias_n[n + 1]; }
                if (Rb) {
                    const float* rp = Rb + (size_t)m * ldc + n;
                    v0 += rp[0]; v1 += rp[1];
                }
                v0 *= alpha; v1 *= alpha;
                if (Chb) {
                    *reinterpret_cast<__half2*>(Chb + (size_t)m * ldc + n) =
                        __floats2half2_rn(v0, v1);
                } else {
                    float2 f2 = make_float2(v0, v1);
                    *reinterpret_cast<float2*>(Cfb + (size_t)m * ldc + n) = f2;
                }
            }
        }
    }
}

// ===================== Softmax (MUFU-free, base-2) =========================
__device__ __forceinline__ float fexp2(float x) {
    x = fmaxf(x, -120.f);
    float k = rintf(x);
    float r = x - k;
    float p = 0.0013333558f;
    p = fmaf(p, r, 0.0096181291f);
    p = fmaf(p, r, 0.0555041087f);
    p = fmaf(p, r, 0.2402265069f);
    p = fmaf(p, r, 0.6931471806f);
    p = fmaf(p, r, 1.0f);
    return p * __int_as_float(((int)k + 127) << 23);
}

__global__ __launch_bounds__(256) void softmax_h(__half* __restrict__ st)
{
    size_t row = ((size_t)blockIdx.y * HW_ + blockIdx.x) * HW_;
    uint4* p = reinterpret_cast<uint4*>(st + row);
    int t = threadIdx.x;

    uint4 u[2];
    u[0] = p[t];
    u[1] = p[t + 256];
    float f[16];
    #pragma unroll
    for (int e = 0; e < 2; e++) {
        const uint32_t* w = &u[e].x;
        #pragma unroll
        for (int j = 0; j < 4; j++) {
            float2 v = __half22float2(*reinterpret_cast<const __half2*>(&w[j]));
            f[e * 8 + 2 * j]     = v.x;
            f[e * 8 + 2 * j + 1] = v.y;
        }
    }

    float mx = -1e30f;
    #pragma unroll
    for (int e = 0; e < 16; e++) mx = fmaxf(mx, f[e]);
    __shared__ float red[8];
    #pragma unroll
    for (int o = 16; o; o >>= 1) mx = fmaxf(mx, __shfl_xor_sync(0xffffffffu, mx, o));
    if ((t & 31) == 0) red[t >> 5] = mx;
    __syncthreads();
    float bmx = red[0];
    #pragma unroll
    for (int i = 1; i < 8; i++) bmx = fmaxf(bmx, red[i]);
    __syncthreads();

    float s = 0.f;
    #pragma unroll
    for (int e = 0; e < 16; e++) { f[e] = fexp2(f[e] - bmx); s += f[e]; }
    #pragma unroll
    for (int o = 16; o; o >>= 1) s += __shfl_xor_sync(0xffffffffu, s, o);
    if ((t & 31) == 0) red[t >> 5] = s;
    __syncthreads();
    float ts = 0.f;
    #pragma unroll
    for (int i = 0; i < 8; i++) ts += red[i];
    float inv = 1.0f / ts;

    #pragma unroll
    for (int e = 0; e < 2; e++) {
        uint32_t* w = &u[e].x;
        #pragma unroll
        for (int j = 0; j < 4; j++) {
            __half2 h = __floats2half2_rn(f[e * 8 + 2 * j] * inv,
                                          f[e * 8 + 2 * j + 1] * inv);
            w[j] = *reinterpret_cast<uint32_t*>(&h);
        }
    }
    p[t]       = u[0];
    p[t + 256] = u[1];
}

// ============================ Launcher =====================================
extern "C" void kernel_launch(void* const* d_in, const int* in_sizes, int n_in,
                              void* d_out, int out_size)
{
    const float* q     = (const float*)d_in[0];
    const float* gamma = (const float*)d_in[1];
    const float* beta  = (const float*)d_in[2];
    const float* wq    = (const float*)d_in[3];
    const float* bq    = (const float*)d_in[4];
    const float* wk    = (const float*)d_in[5];
    const float* bk    = (const float*)d_in[6];
    const float* wv    = (const float*)d_in[7];
    const float* bv    = (const float*)d_in[8];
    const float* wo    = (const float*)d_in[9];
    const float* bo    = (const float*)d_in[10];
    float* out = (float*)d_out;

    __half *xt, *qt, *kt, *v, *st, *ot, *wh;
    float2* stats;
    cudaGetSymbolAddress((void**)&xt, g_xt);
    cudaGetSymbolAddress((void**)&qt, g_qt);
    cudaGetSymbolAddress((void**)&kt, g_kt);
    cudaGetSymbolAddress((void**)&v,  g_v);
    cudaGetSymbolAddress((void**)&st, g_st);
    cudaGetSymbolAddress((void**)&ot, g_ot);
    cudaGetSymbolAddress((void**)&wh, g_wh);
    cudaGetSymbolAddress((void**)&stats, g_stats);
    __half* wqh = wh;
    __half* wkh = wh + (size_t)C_ * C_;
    __half* wvh = wh + 2 * (size_t)C_ * C_;
    __half* woh = wh + 3 * (size_t)C_ * C_;

    static int smem_set = 0;
    if (!smem_set) {
        cudaFuncSetAttribute(mm_h, cudaFuncAttributeMaxDynamicSharedMemorySize,
                             SMEM_SZ);
        smem_set = 1;
    }

    const long CB = (long)C_ * HW_;
    const long SB = (long)HW_ * HW_;

    f2h4_kernel<<<(4 * C_ * C_ / 4) / 256, 256>>>(wq, wk, wv, wo, wh);

    gn_stats<<<B_ * NG_, 256>>>(q, stats);
    gn_apply_t<<<dim3(HW_ / 32, C_ / 32, B_), 256>>>(q, stats, gamma, beta, xt);

    dim3 gP(C_ / BN, HW_ / BM, B_);
    mm_h<<<gP, 128, SMEM_SZ>>>(xt, C_, CB,  wqh, C_, 0,
                               qt, nullptr, C_, CB,
                               nullptr, bq, nullptr, 0, 1.0f, C_ / BK);
    mm_h<<<gP, 128, SMEM_SZ>>>(xt, C_, CB,  wkh, C_, 0,
                               kt, nullptr, C_, CB,
                               nullptr, bk, nullptr, 0, 1.0f, C_ / BK);

    dim3 gV(HW_ / BN, C_ / BM, B_);
    mm_h<<<gV, 128, SMEM_SZ>>>(wvh, C_, 0,  xt, C_, CB,
                               v, nullptr, HW_, CB,
                               bv, nullptr, nullptr, 0, 1.0f, C_ / BK);

    dim3 gS(HW_ / BN, HW_ / BM, B_);
    mm_h<<<gS, 128, SMEM_SZ>>>(qt, C_, CB,  kt, C_, CB,
                               st, nullptr, HW_, SB,
                               nullptr, nullptr, nullptr, 0,
                               0.044194173824159216f * 1.4426950408889634f,
                               C_ / BK);

    softmax_h<<<dim3(HW_, B_), 256>>>(st);

    mm_h<<<gP, 128, SMEM_SZ>>>(st, HW_, SB,  v, HW_, CB,
                               ot, nullptr, C_, CB,
                               nullptr, nullptr, nullptr, 0, 1.0f, HW_ / BK);

    mm_h<<<gV, 128, SMEM_SZ>>>(woh, C_, 0,  ot, C_, CB,
                               nullptr, out, HW_, CB,
                               bo, nullptr, q, CB,
                               0.7071067811865476f, C_ / BK);
}

// round 7
// speedup vs baseline: 9.8092x; 1.0145x over previous
#include <cuda_runtime.h>
#include <cuda_fp16.h>
#include <cstdint>
#include <math.h>

// ---------------------------------------------------------------------------
// Attention2D (b=4, c=512, hw=4096) — Round 7.
//  - GEMM inner loop: B-fragment streaming (LDSM of next B pair overlapped
//    with MMAs of current pair), frees 8 regs vs R6.
//  - Q and K projections merged into one N=1024 GEMM (wq|wk contiguous).
// ---------------------------------------------------------------------------

#define B_  4
#define C_  512
#define HW_ 4096
#define NG_ 32
#define CPG_ (C_ / NG_)
#define GRP_ELEMS (CPG_ * HW_)

__device__ __align__(256) __half g_xt[(size_t)B_ * HW_ * C_];
__device__ __align__(256) __half g_qk[(size_t)B_ * HW_ * 1024];  // [j][qk 1024]
__device__ __align__(256) __half g_v [(size_t)B_ * C_ * HW_];
__device__ __align__(256) __half g_st[(size_t)B_ * HW_ * HW_];
__device__ __align__(256) __half g_ot[(size_t)B_ * HW_ * C_];
__device__ __align__(256) __half g_wh[4][(size_t)C_ * C_];
__device__ float  g_bqk[1024];
__device__ float2 g_stats[B_ * NG_];

// ============================ small kernels ================================
__global__ __launch_bounds__(256) void f2h4_kernel(
    const float* __restrict__ w0, const float* __restrict__ w1,
    const float* __restrict__ w2, const float* __restrict__ w3,
    __half* __restrict__ o)
{
    const int n4 = C_ * C_ / 4;
    int i = blockIdx.x * blockDim.x + threadIdx.x;
    int w = i >> 16;
    int e = i & (n4 - 1);
    const float* src = (w == 0) ? w0 : (w == 1) ? w1 : (w == 2) ? w2 : w3;
    float4 v = reinterpret_cast<const float4*>(src)[e];
    __half2 h0 = __floats2half2_rn(v.x, v.y);
    __half2 h1 = __floats2half2_rn(v.z, v.w);
    __half2* dst = reinterpret_cast<__half2*>(o + (size_t)w * C_ * C_);
    dst[2 * e] = h0;
    dst[2 * e + 1] = h1;
}

__global__ __launch_bounds__(256) void bias_cat_kernel(
    const float* __restrict__ bq, const float* __restrict__ bk,
    float* __restrict__ o)
{
    int i = blockIdx.x * blockDim.x + threadIdx.x;   // 0..1023
    o[i] = (i < C_) ? bq[i] : bk[i - C_];
}

__global__ __launch_bounds__(256) void gn_stats(
    const float* __restrict__ x, float2* __restrict__ stats)
{
    int b = blockIdx.x / NG_, g = blockIdx.x % NG_;
    size_t base = ((size_t)b * C_ + (size_t)g * CPG_) * HW_;
    const float4* x4 = reinterpret_cast<const float4*>(x + base);
    int t = threadIdx.x;
    float s = 0.f, ss = 0.f;
    for (int i = t; i < GRP_ELEMS / 4; i += 256) {
        float4 v = x4[i];
        s  += v.x + v.y + v.z + v.w;
        ss += v.x * v.x + v.y * v.y + v.z * v.z + v.w * v.w;
    }
    __shared__ float rs[8], rss[8];
    #pragma unroll
    for (int o = 16; o; o >>= 1) {
        s  += __shfl_xor_sync(0xffffffffu, s,  o);
        ss += __shfl_xor_sync(0xffffffffu, ss, o);
    }
    if ((t & 31) == 0) { rs[t >> 5] = s; rss[t >> 5] = ss; }
    __syncthreads();
    if (t == 0) {
        float ts = 0.f, tss = 0.f;
        #pragma unroll
        for (int i = 0; i < 8; i++) { ts += rs[i]; tss += rss[i]; }
        float inv_n = 1.0f / (float)GRP_ELEMS;
        float mu = ts * inv_n;
        float var = tss * inv_n - mu * mu;
        stats[blockIdx.x] = make_float2(mu, rsqrtf(var + 1e-6f));
    }
}

__global__ __launch_bounds__(256) void gn_apply_t(
    const float* __restrict__ x, const float2* __restrict__ stats,
    const float* __restrict__ gamma, const float* __restrict__ beta,
    __half* __restrict__ xt)
{
    __shared__ float tile[32][33];
    int j0 = blockIdx.x * 32, c0 = blockIdx.y * 32, b = blockIdx.z;
    int tx = threadIdx.x & 31, ty = threadIdx.x >> 5;
    size_t xb = (size_t)b * C_ * HW_;
    #pragma unroll
    for (int it = 0; it < 4; it++) {
        int c = c0 + ty + it * 8;
        float v = x[xb + (size_t)c * HW_ + j0 + tx];
        float2 s = stats[b * NG_ + (c >> 4)];
        tile[ty + it * 8][tx] = (v - s.x) * s.y * gamma[c] + beta[c];
    }
    __syncthreads();
    size_t tb = (size_t)b * HW_ * C_;
    #pragma unroll
    for (int it = 0; it < 4; it++) {
        int j = j0 + ty + it * 8;
        xt[tb + (size_t)j * C_ + c0 + tx] = __float2half(tile[tx][ty + it * 8]);
    }
}

// ========================= fp16 mma.sync GEMM ==============================
#define BM 128
#define BN 128
#define BK 64
#define NSTAGE 3
#define STAGE_B (2 * BM * BK)
#define SMEM_SZ (NSTAGE * 2 * STAGE_B)   // 96 KB

__device__ __forceinline__ uint32_t smem_u32(const void* p) {
    uint32_t a;
    asm("{ .reg .u64 t; cvta.to.shared.u64 t, %1; cvt.u32.u64 %0, t; }"
        : "=r"(a) : "l"(p));
    return a;
}

__device__ __forceinline__ void load_tile_h(
    uint32_t sdst, const __half* __restrict__ src, long ld, int tid)
{
    #pragma unroll
    for (int i = 0; i < 8; i++) {
        int idx = tid + (i << 7);
        int r = idx >> 3;
        int c = idx & 7;
        uint32_t sw = (uint32_t)r * 128 + (uint32_t)((c ^ (r & 7)) << 4);
        asm volatile("cp.async.cg.shared.global [%0], [%1], 16;"
                     :: "r"(sdst + sw), "l"(src + (long)r * ld + (c << 3))
                     : "memory");
    }
}

#define LDSM4(r0, r1, r2, r3, a)                                           \
    asm volatile("ldmatrix.sync.aligned.m8n8.x4.shared.b16 {%0,%1,%2,%3}, [%4];" \
                 : "=r"(r0), "=r"(r1), "=r"(r2), "=r"(r3) : "r"(a))

#define MMA16816(acc, a0, a1, a2, a3, b0, b1)                               \
    asm volatile(                                                           \
        "mma.sync.aligned.m16n8k16.row.col.f32.f16.f16.f32 "                \
        "{%0,%1,%2,%3}, {%4,%5,%6,%7}, {%8,%9}, {%0,%1,%2,%3};"             \
        : "+f"((acc)[0]), "+f"((acc)[1]), "+f"((acc)[2]), "+f"((acc)[3])    \
        : "r"(a0), "r"(a1), "r"(a2), "r"(a3), "r"(b0), "r"(b1))

__global__ __launch_bounds__(128, 2) void mm_h(
    const __half* __restrict__ A, long lda, long asb,
    const __half* __restrict__ Bp, long ldb, long bsb,
    __half* __restrict__ Ch, float* __restrict__ Cf, long ldc, long csb,
    const float* __restrict__ bias_m, const float* __restrict__ bias_n,
    const float* __restrict__ res, long rsb, float alpha, int T)
{
    extern __shared__ __half smem[];
    uint32_t sb = smem_u32(smem);
    uint32_t sA[NSTAGE], sB[NSTAGE];
    #pragma unroll
    for (int s = 0; s < NSTAGE; s++) {
        sA[s] = sb + (uint32_t)s * 2 * STAGE_B;
        sB[s] = sA[s] + STAGE_B;
    }

    int tid = threadIdx.x, lane = tid & 31, wid = tid >> 5;
    int wm = wid >> 1, wn = wid & 1;        // 2x2 warp grid, 64x64 tiles
    int bz = blockIdx.z;
    int m0 = blockIdx.y * BM, n0 = blockIdx.x * BN;

    const __half* Ab = A  + (size_t)bz * asb + (size_t)m0 * lda;
    const __half* Bb = Bp + (size_t)bz * bsb + (size_t)n0 * ldb;

    float acc[4][8][4];
    #pragma unroll
    for (int i = 0; i < 4; i++)
        #pragma unroll
        for (int j = 0; j < 8; j++)
            #pragma unroll
            for (int k = 0; k < 4; k++) acc[i][j][k] = 0.f;

    int a_r  = (lane & 7) | (((lane >> 3) & 1) << 3);
    int a_cs = lane >> 4;
    int b_r  = (lane & 7) | (((lane >> 4) & 1) << 3);
    int b_cs = (lane >> 3) & 1;
    // precomputed per-thread base addresses (row part only varies with mt/p)
    uint32_t aRow = (uint32_t)(wm * 64 + a_r);
    uint32_t bRow = (uint32_t)(wn * 64 + b_r);

    load_tile_h(sA[0], Ab, lda, tid);
    load_tile_h(sB[0], Bb, ldb, tid);
    asm volatile("cp.async.commit_group;");
    if (T > 1) {
        load_tile_h(sA[1], Ab + (size_t)BK, lda, tid);
        load_tile_h(sB[1], Bb + (size_t)BK, ldb, tid);
    }
    asm volatile("cp.async.commit_group;");

    for (int t = 0; t < T; t++) {
        int cs = t % NSTAGE;
        asm volatile("cp.async.wait_group 1;");
        __syncthreads();

        if (t + 2 < T) {
            int ns = (t + 2) % NSTAGE;
            load_tile_h(sA[ns], Ab + (size_t)(t + 2) * BK, lda, tid);
            load_tile_h(sB[ns], Bb + (size_t)(t + 2) * BK, ldb, tid);
        }
        asm volatile("cp.async.commit_group;");

        #pragma unroll
        for (int ks = 0; ks < 4; ks++) {
            int ach = ks * 2 + a_cs;
            int bch = ks * 2 + b_cs;

            // B pair 0 first (stream), then all A fragments
            uint32_t b0[4], b1[4];
            {
                uint32_t row = bRow;
                uint32_t addr = sB[cs] + row * 128
                              + (uint32_t)((bch ^ (row & 7)) << 4);
                LDSM4(b0[0], b0[1], b0[2], b0[3], addr);
            }
            uint32_t a[4][4];
            #pragma unroll
            for (int mt = 0; mt < 4; mt++) {
                uint32_t row = aRow + mt * 16;
                uint32_t addr = sA[cs] + row * 128
                              + (uint32_t)((ach ^ (row & 7)) << 4);
                LDSM4(a[mt][0], a[mt][1], a[mt][2], a[mt][3], addr);
            }

            #pragma unroll
            for (int p = 0; p < 4; p++) {
                uint32_t* bc = (p & 1) ? b1 : b0;
                uint32_t* bn = (p & 1) ? b0 : b1;
                if (p < 3) {
                    uint32_t row = bRow + (p + 1) * 16;
                    uint32_t addr = sB[cs] + row * 128
                                  + (uint32_t)((bch ^ (row & 7)) << 4);
                    LDSM4(bn[0], bn[1], bn[2], bn[3], addr);
                }
                #pragma unroll
                for (int mt = 0; mt < 4; mt++) {
                    MMA16816(acc[mt][2 * p],     a[mt][0], a[mt][1], a[mt][2], a[mt][3],
                             bc[0], bc[1]);
                    MMA16816(acc[mt][2 * p + 1], a[mt][0], a[mt][1], a[mt][2], a[mt][3],
                             bc[2], bc[3]);
                }
            }
        }
    }

    // ------------------------------ epilogue -------------------------------
    int mb = m0 + wm * 64;
    int nb = n0 + wn * 64;
    int r0 = lane >> 2, c0 = (lane & 3) * 2;
    __half* Chb = Ch ? Ch + (size_t)bz * csb : nullptr;
    float*  Cfb = Cf ? Cf + (size_t)bz * csb : nullptr;
    const float* Rb = res ? res + (size_t)bz * rsb : nullptr;

    #pragma unroll
    for (int mt = 0; mt < 4; mt++) {
        #pragma unroll
        for (int h = 0; h < 2; h++) {
            int m = mb + mt * 16 + r0 + h * 8;
            float bmv = bias_m ? bias_m[m] : 0.f;
            #pragma unroll
            for (int nt = 0; nt < 8; nt++) {
                int n = nb + nt * 8 + c0;
                float v0 = acc[mt][nt][2 * h + 0];
                float v1 = acc[mt][nt][2 * h + 1];
                v0 += bmv; v1 += bmv;
                if (bias_n) { v0 += bias_n[n]; v1 += bias_n[n + 1]; }
                if (Rb) {
                    const float* rp = Rb + (size_t)m * ldc + n;
                    v0 += rp[0]; v1 += rp[1];
                }
                v0 *= alpha; v1 *= alpha;
                if (Chb) {
                    *reinterpret_cast<__half2*>(Chb + (size_t)m * ldc + n) =
                        __floats2half2_rn(v0, v1);
                } else {
                    float2 f2 = make_float2(v0, v1);
                    *reinterpret_cast<float2*>(Cfb + (size_t)m * ldc + n) = f2;
                }
            }
        }
    }
}

// ===================== Softmax (MUFU-free, base-2) =========================
__device__ __forceinline__ float fexp2(float x) {
    x = fmaxf(x, -120.f);
    float k = rintf(x);
    float r = x - k;
    float p = 0.0013333558f;
    p = fmaf(p, r, 0.0096181291f);
    p = fmaf(p, r, 0.0555041087f);
    p = fmaf(p, r, 0.2402265069f);
    p = fmaf(p, r, 0.6931471806f);
    p = fmaf(p, r, 1.0f);
    return p * __int_as_float(((int)k + 127) << 23);
}

__global__ __launch_bounds__(256) void softmax_h(__half* __restrict__ st)
{
    size_t row = ((size_t)blockIdx.y * HW_ + blockIdx.x) * HW_;
    uint4* p = reinterpret_cast<uint4*>(st + row);
    int t = threadIdx.x;

    uint4 u[2];
    u[0] = p[t];
    u[1] = p[t + 256];
    float f[16];
    #pragma unroll
    for (int e = 0; e < 2; e++) {
        const uint32_t* w = &u[e].x;
        #pragma unroll
        for (int j = 0; j < 4; j++) {
            float2 v = __half22float2(*reinterpret_cast<const __half2*>(&w[j]));
            f[e * 8 + 2 * j]     = v.x;
            f[e * 8 + 2 * j + 1] = v.y;
        }
    }

    float mx = -1e30f;
    #pragma unroll
    for (int e = 0; e < 16; e++) mx = fmaxf(mx, f[e]);
    __shared__ float red[8];
    #pragma unroll
    for (int o = 16; o; o >>= 1) mx = fmaxf(mx, __shfl_xor_sync(0xffffffffu, mx, o));
    if ((t & 31) == 0) red[t >> 5] = mx;
    __syncthreads();
    float bmx = red[0];
    #pragma unroll
    for (int i = 1; i < 8; i++) bmx = fmaxf(bmx, red[i]);
    __syncthreads();

    float s = 0.f;
    #pragma unroll
    for (int e = 0; e < 16; e++) { f[e] = fexp2(f[e] - bmx); s += f[e]; }
    #pragma unroll
    for (int o = 16; o; o >>= 1) s += __shfl_xor_sync(0xffffffffu, s, o);
    if ((t & 31) == 0) red[t >> 5] = s;
    __syncthreads();
    float ts = 0.f;
    #pragma unroll
    for (int i = 0; i < 8; i++) ts += red[i];
    float inv = 1.0f / ts;

    #pragma unroll
    for (int e = 0; e < 2; e++) {
        uint32_t* w = &u[e].x;
        #pragma unroll
        for (int j = 0; j < 4; j++) {
            __half2 h = __floats2half2_rn(f[e * 8 + 2 * j] * inv,
                                          f[e * 8 + 2 * j + 1] * inv);
            w[j] = *reinterpret_cast<uint32_t*>(&h);
        }
    }
    p[t]       = u[0];
    p[t + 256] = u[1];
}

// ============================ Launcher =====================================
extern "C" void kernel_launch(void* const* d_in, const int* in_sizes, int n_in,
                              void* d_out, int out_size)
{
    const float* q     = (const float*)d_in[0];
    const float* gamma = (const float*)d_in[1];
    const float* beta  = (const float*)d_in[2];
    const float* wq    = (const float*)d_in[3];
    const float* bq    = (const float*)d_in[4];
    const float* wk    = (const float*)d_in[5];
    const float* bk    = (const float*)d_in[6];
    const float* wv    = (const float*)d_in[7];
    const float* bv    = (const float*)d_in[8];
    const float* wo    = (const float*)d_in[9];
    const float* bo    = (const float*)d_in[10];
    float* out = (float*)d_out;

    __half *xt, *qk, *v, *st, *ot, *wh;
    float *bqk;
    float2* stats;
    cudaGetSymbolAddress((void**)&xt, g_xt);
    cudaGetSymbolAddress((void**)&qk, g_qk);
    cudaGetSymbolAddress((void**)&v,  g_v);
    cudaGetSymbolAddress((void**)&st, g_st);
    cudaGetSymbolAddress((void**)&ot, g_ot);
    cudaGetSymbolAddress((void**)&wh, g_wh);
    cudaGetSymbolAddress((void**)&bqk, g_bqk);
    cudaGetSymbolAddress((void**)&stats, g_stats);
    __half* wqh = wh;                              // wq|wk contiguous: N=1024
    __half* wvh = wh + 2 * (size_t)C_ * C_;
    __half* woh = wh + 3 * (size_t)C_ * C_;

    static int smem_set = 0;
    if (!smem_set) {
        cudaFuncSetAttribute(mm_h, cudaFuncAttributeMaxDynamicSharedMemorySize,
                             SMEM_SZ);
        smem_set = 1;
    }

    const long CB  = (long)C_ * HW_;
    const long QKB = (long)HW_ * 1024;
    const long SB  = (long)HW_ * HW_;

    f2h4_kernel<<<(4 * C_ * C_ / 4) / 256, 256>>>(wq, wk, wv, wo, wh);
    bias_cat_kernel<<<4, 256>>>(bq, bk, bqk);

    gn_stats<<<B_ * NG_, 256>>>(q, stats);
    gn_apply_t<<<dim3(HW_ / 32, C_ / 32, B_), 256>>>(q, stats, gamma, beta, xt);

    // QK merged: M=4096(j), N=1024(q|k channels), K=512
    dim3 gQK(1024 / BN, HW_ / BM, B_);   // (8, 32, 4)
    mm_h<<<gQK, 128, SMEM_SZ>>>(xt, C_, CB,  wqh, C_, 0,
                                qk, nullptr, 1024, QKB,
                                nullptr, bqk, nullptr, 0, 1.0f, C_ / BK);

    // V[c][i]: M=512(c), N=4096(i), K=512
    dim3 gV(HW_ / BN, C_ / BM, B_);
    mm_h<<<gV, 128, SMEM_SZ>>>(wvh, C_, 0,  xt, C_, CB,
                               v, nullptr, HW_, CB,
                               bv, nullptr, nullptr, 0, 1.0f, C_ / BK);

    // ST[j][i] = (scale*log2e) * Q @ K^T: A=qk[:, :512], B=qk[:, 512:]
    dim3 gS(HW_ / BN, HW_ / BM, B_);
    mm_h<<<gS, 128, SMEM_SZ>>>(qk, 1024, QKB,  qk + 512, 1024, QKB,
                               st, nullptr, HW_, SB,
                               nullptr, nullptr, nullptr, 0,
                               0.044194173824159216f * 1.4426950408889634f,
                               C_ / BK);

    softmax_h<<<dim3(HW_, B_), 256>>>(st);

    // Ot[j][c] = ST @ V^T: M=4096(j), N=512(c), K=4096
    dim3 gP(C_ / BN, HW_ / BM, B_);
    mm_h<<<gP, 128, SMEM_SZ>>>(st, HW_, SB,  v, HW_, CB,
                               ot, nullptr, C_, CB,
                               nullptr, nullptr, nullptr, 0, 1.0f, HW_ / BK);

    // out[c][j] = (Wo @ Ot^T + bo + q) * inv_sqrt2
    mm_h<<<gV, 128, SMEM_SZ>>>(woh, C_, 0,  ot, C_, CB,
                               nullptr, out, HW_, CB,
                               bo, nullptr, q, CB,
                               0.7071067811865476f, C_ / BK);
}